// round 14
// baseline (speedup 1.0000x reference)
#include <cuda_runtime.h>
#include <cuda_fp16.h>
#include <math.h>
#include <stdint.h>

#define TT 8
#define SS 14
#define LL 196            // S*S
#define NB 8
#define CC 1024
#define NH 16
#define HD 64
#define NTOK (1 + LL*TT)  // 1569
#define ROWS (NTOK*NB)    // 12552
#define PROWS (LL*TT*NB)  // 12544 patch rows
#define LS (LL + 1)       // 197 spatial seq
#define SB (TT*NB)        // 64 spatial batch
#define SROWS (LS*SB)     // 12608
#define BH   1024         // SB*NH spatial batch*heads
#define SKP 200           // S row pad (floats)
#define PKP 256           // P/Vt key pad (halves, mult of 64 for BK=64)

// ---------------- scratch (device globals; no allocations) ----------------
__device__ __align__(256) float  g_XBUF[(size_t)ROWS * CC];      // residual stream
__device__ __align__(256) __half g_LNh [(size_t)SROWS * CC];     // LN out (fp16)
__device__ __align__(256) __half g_QKVh[(size_t)SROWS * 3 * CC]; // qkv fp16
__device__ __align__(256) __half g_ATTh[(size_t)SROWS * CC];     // attn out (fp16)
__device__ __align__(256) float  g_PROJ[(size_t)SROWS * CC];     // spatial proj out
__device__ __align__(256) float  g_XT  [(size_t)PROWS * CC];     // xt_full fp32
__device__ __align__(256) __half g_Hh  [(size_t)ROWS * 4 * CC];  // MLP hidden (fp16)
__device__ __align__(256) __half g_WTh [16777216];               // fp16 weights
__device__ __align__(256) float  g_S   [(size_t)BH * LS * SKP];  // spatial scores fp32
__device__ __align__(256) __half g_P   [(size_t)BH * LS * PKP];  // probs fp16 (padded)
__device__ __align__(256) __half g_Vt  [(size_t)BH * HD * PKP];  // V^T fp16 (padded)
__device__ float g_ZERO[256];                                    // zero bias

// ---------------- merged weight prep: fp32 -> fp16 (all 6 tensors) --------
struct W6 { const float* p[6]; };
__global__ void wprep_all_kernel(W6 ws, __half* __restrict__ d) {
    const int cum1 = 786432, cum2 = 1048576, cum3 = 1835008,
              cum4 = 2097152, cum5 = 3145728, cum6 = 4194304;
    int i = blockIdx.x * 256 + threadIdx.x;
    if (i >= cum6) return;
    int s; int base;
    if      (i < cum1) { s = 0; base = 0; }
    else if (i < cum2) { s = 1; base = cum1; }
    else if (i < cum3) { s = 2; base = cum2; }
    else if (i < cum4) { s = 3; base = cum3; }
    else if (i < cum5) { s = 4; base = cum4; }
    else               { s = 5; base = cum5; }
    float4 v = ((const float4*)ws.p[s])[i - base];
    ((__half2*)d)[i * 2]     = __floats2half2_rn(v.x, v.y);
    ((__half2*)d)[i * 2 + 1] = __floats2half2_rn(v.z, v.w);
}

// ---------------- Stage 1 fused: depthwise conv pos-embed + LayerNorm_t ----
__global__ void __launch_bounds__(256)
pos_ln_kernel(const float* __restrict__ x, const float* __restrict__ pw,
              const float* __restrict__ pb,
              const float* __restrict__ g, const float* __restrict__ b) {
    __shared__ float rows[TT][CC];
    __shared__ float reds[8][TT], reds2[8][TT];
    __shared__ float stat[TT][2];
    int l = blockIdx.x, n = blockIdx.y, tid = threadIdx.x;
    int i = l / SS, j = l % SS;
    int wid = tid >> 5, lane = tid & 31;
    float s[TT], s2[TT];
    #pragma unroll
    for (int t = 0; t < TT; t++) { s[t] = 0.f; s2[t] = 0.f; }

    if (l == 0) {
        for (int c = tid; c < CC; c += 256)
            g_XBUF[(size_t)n * CC + c] = x[(size_t)n * CC + c];
    }

    for (int ci = 0; ci < 4; ci++) {
        int c = ci * 256 + tid;
        float w[27];
        #pragma unroll
        for (int k = 0; k < 27; k++) w[k] = pw[(size_t)c * 27 + k];
        float acc[TT], xown[TT];
        #pragma unroll
        for (int t = 0; t < TT; t++) acc[t] = pb[c];
        #pragma unroll
        for (int di = 0; di < 3; di++) {
            int i2 = i + di - 1;
            if ((unsigned)i2 >= SS) continue;
            #pragma unroll
            for (int dj = 0; dj < 3; dj++) {
                int j2 = j + dj - 1;
                if ((unsigned)j2 >= SS) continue;
                int kidx = di * 3 + dj;
                const float* base = x + ((size_t)(1 + (i2 * SS + j2) * TT) * NB + n) * CC + c;
                bool cen = (di == 1 && dj == 1);
                #pragma unroll
                for (int t2 = 0; t2 < TT; t2++) {
                    float val = base[(size_t)t2 * NB * CC];
                    if (cen) xown[t2] = val;
                    if (t2 + 1 < TT) acc[t2 + 1] += w[kidx]      * val;
                    acc[t2]                      += w[9  + kidx] * val;
                    if (t2 > 0)      acc[t2 - 1] += w[18 + kidx] * val;
                }
            }
        }
        #pragma unroll
        for (int t = 0; t < TT; t++) {
            float v = xown[t] + acc[t];
            g_XBUF[((size_t)((1 + l * TT + t) * NB) + n) * CC + c] = v;
            rows[t][c] = v;
            s[t] += v; s2[t] += v * v;
        }
    }
    #pragma unroll
    for (int t = 0; t < TT; t++)
        for (int m = 16; m; m >>= 1) {
            s[t]  += __shfl_xor_sync(~0u, s[t],  m);
            s2[t] += __shfl_xor_sync(~0u, s2[t], m);
        }
    if (lane == 0) {
        #pragma unroll
        for (int t = 0; t < TT; t++) { reds[wid][t] = s[t]; reds2[wid][t] = s2[t]; }
    }
    __syncthreads();
    if (lane < 8) {
        float a = reds[lane][wid], a2 = reds2[lane][wid];
        #pragma unroll
        for (int m = 4; m; m >>= 1) {
            a  += __shfl_xor_sync(0xffu, a,  m);
            a2 += __shfl_xor_sync(0xffu, a2, m);
        }
        if (lane == 0) {
            float mean = a * (1.f / CC);
            float var  = a2 * (1.f / CC) - mean * mean;
            stat[wid][0] = mean;
            stat[wid][1] = rsqrtf(var + 1e-5f);
        }
    }
    __syncthreads();
    for (int ci = 0; ci < 4; ci++) {
        int c = ci * 256 + tid;
        float gc = g[c], bc = b[c];
        #pragma unroll
        for (int t = 0; t < TT; t++) {
            float v = rows[t][c];
            g_LNh[((size_t)((l * TT + t) * NB) + n) * CC + c] =
                __float2half_rn((v - stat[t][0]) * stat[t][1] * gc + bc);
        }
    }
}

// ---------------- LayerNorm (mode 1: spatial gather) -> fp16 ---------------
__global__ void ln_kernel(const float* __restrict__ src,
                          const float* __restrict__ srcCls,
                          __half* __restrict__ dst,
                          const float* __restrict__ g, const float* __restrict__ b,
                          int mode, int srcOff) {
    int row = blockIdx.x;
    const float* xr;
    if (mode == 0) {
        xr = src + (size_t)(row + srcOff) * CC;
    } else {
        int ls = row / SB, bb = row % SB;
        int t = bb / NB, n = bb % NB;
        if (ls == 0) xr = srcCls + (size_t)n * CC;
        else         xr = src + (size_t)(((ls - 1) * TT + t) * NB + n) * CC;
    }
    int tid = threadIdx.x;
    float s = 0.f, s2 = 0.f;
    float v[4];
    #pragma unroll
    for (int it = 0; it < 4; it++) {
        float val = xr[tid + it * 256];
        v[it] = val; s += val; s2 += val * val;
    }
    __shared__ float red[2][8];
    for (int m = 16; m; m >>= 1) {
        s  += __shfl_xor_sync(~0u, s, m);
        s2 += __shfl_xor_sync(~0u, s2, m);
    }
    if ((tid & 31) == 0) { red[0][tid >> 5] = s; red[1][tid >> 5] = s2; }
    __syncthreads();
    s = 0.f; s2 = 0.f;
    #pragma unroll
    for (int w = 0; w < 8; w++) { s += red[0][w]; s2 += red[1][w]; }
    float mean = s * (1.f / CC);
    float var  = s2 * (1.f / CC) - mean * mean;
    float inv  = rsqrtf(var + 1e-5f);
    __half* dr = dst + (size_t)row * CC;
    #pragma unroll
    for (int it = 0; it < 4; it++) {
        int c = tid + it * 256;
        dr[c] = __float2half_rn((v[it] - mean) * inv * g[c] + b[c]);
    }
}

// ---------------- fused spatial residual + LayerNorm2 ----------------------
__global__ void resid_ln_kernel(const float* __restrict__ g,
                                const float* __restrict__ b) {
    int row = blockIdx.x, tid = threadIdx.x;
    int token = row >> 3, n = row & 7;
    float v[4];
    float s = 0.f, s2 = 0.f;
    #pragma unroll
    for (int it = 0; it < 4; it++) {
        int c = tid + it * 256;
        float base = g_XBUF[(size_t)row * CC + c];
        float add;
        if (token == 0) {
            float a = 0.f;
            #pragma unroll
            for (int t = 0; t < TT; t++)
                a += g_PROJ[((size_t)(t * NB + n)) * CC + c];
            add = a * 0.125f;
        } else {
            int p = token - 1;
            int l = p >> 3, t = p & 7;
            add = g_PROJ[((size_t)((l + 1) * SB + t * NB + n)) * CC + c];
        }
        float vv = base + add;
        g_XBUF[(size_t)row * CC + c] = vv;
        v[it] = vv; s += vv; s2 += vv * vv;
    }
    __shared__ float red[2][8];
    for (int m = 16; m; m >>= 1) {
        s  += __shfl_xor_sync(~0u, s, m);
        s2 += __shfl_xor_sync(~0u, s2, m);
    }
    if ((tid & 31) == 0) { red[0][tid >> 5] = s; red[1][tid >> 5] = s2; }
    __syncthreads();
    s = 0.f; s2 = 0.f;
    #pragma unroll
    for (int w = 0; w < 8; w++) { s += red[0][w]; s2 += red[1][w]; }
    float mean = s * (1.f / CC);
    float var  = s2 * (1.f / CC) - mean * mean;
    float inv  = rsqrtf(var + 1e-5f);
    __half* dr = g_LNh + (size_t)row * CC;
    #pragma unroll
    for (int it = 0; it < 4; it++) {
        int c = tid + it * 256;
        dr[c] = __float2half_rn((v[it] - mean) * inv * g[c] + b[c]);
    }
}

// ---------------- fp16 tensor-core GEMM, cp.async + ldmatrix, BK=64 --------
// C[M,N] = A[M,K] @ B[N,K]^T + bias (+epilogue). Strided rows, batched.
// MODE 0: fp32 store | 1: QuickGELU->fp16 | 2: residual add fp32 | 3: fp16 store
// BATCH 0: none | 1: qkv-layout A/B (scores), S-out | 2: P/Vt in, qkv-scatter out
// 128x128 tile, BK=64 halves, 3 smem stages, 16 syncs per K=1024.
#define HSTR 72
#define STAGE_HALF (2 * 128 * HSTR)            // 18432 halves = 36864 B
#define GSTAGES 3
#define GSMEM_BYTES (GSTAGES * STAGE_HALF * 2) // 110592

template<int MODE, int BATCH>
__global__ void __launch_bounds__(256, 2)
tgemm_kernel(const __half* __restrict__ A, size_t strideA,
             const __half* __restrict__ B, size_t strideB,
             const float* __restrict__ bias, const float* __restrict__ res,
             void* __restrict__ outv, size_t outStride,
             int M, int N, int K, int colLim) {
    extern __shared__ __half smh[];
    const int tid  = threadIdx.x;
    const int bm   = blockIdx.y * 128, bn = blockIdx.x * 128;
    const int z    = blockIdx.z;
    const int lane = tid & 31, wid = tid >> 5;
    const int wm   = (wid & 1) << 6;
    const int wn   = (wid >> 1) << 5;

    size_t aoff = 0, boff = 0, ooff = 0;
    if (BATCH == 1) {
        size_t e = (size_t)(z >> 4) * 3072 + (size_t)(z & 15) * 64;
        aoff = e; boff = e;
        ooff = (size_t)z * LS * SKP;
    } else if (BATCH == 2) {
        aoff = (size_t)z * LS * PKP;
        boff = (size_t)z * HD * PKP;
        ooff = (size_t)(z >> 4) * 1024 + (size_t)(z & 15) * 64;
    }

    const int  lrow  = tid & 127;
    const bool loadA = tid < 128;
    int  growi = loadA ? (bm + lrow) : (bn + lrow);
    const bool valid = loadA ? (growi < M) : (growi < N);
    const int  vsz   = valid ? 16 : 0;
    if (!valid) growi = 0;
    const __half* gRow = (loadA ? (A + aoff) : (B + boff))
                       + (size_t)growi * (loadA ? strideA : strideB);
    unsigned sbase = (unsigned)__cvta_generic_to_shared(smh);
    const unsigned dRowOff = (loadA ? 0u : 128u * HSTR * 2) + lrow * (HSTR * 2);

    // ldmatrix per-lane byte offsets (within a stage)
    unsigned aoff_lm[4], boff_lm[2];
    #pragma unroll
    for (int mt = 0; mt < 4; mt++)
        aoff_lm[mt] = (unsigned)(((wm + mt * 16 + (lane & 15)) * HSTR
                                  + ((lane >> 4) << 3)) * 2);
    #pragma unroll
    for (int p = 0; p < 2; p++)
        boff_lm[p] = (unsigned)(((128 + wn + (2 * p + (lane >> 4)) * 8 + (lane & 7)) * HSTR
                                 + (((lane >> 3) & 1) << 3)) * 2);

    float acc[16][4];
    #pragma unroll
    for (int i = 0; i < 16; i++)
        #pragma unroll
        for (int j = 0; j < 4; j++) acc[i][j] = 0.f;

    const int NS = K >> 6;   // 64 halves per slab

    // prologue: fill stages 0..GSTAGES-2
    #pragma unroll
    for (int s = 0; s < GSTAGES - 1; s++) {
        if (s < NS) {
            unsigned d = sbase + (unsigned)(s * STAGE_HALF * 2) + dRowOff;
            const __half* gp = gRow + s * 64;
            #pragma unroll
            for (int c = 0; c < 8; c++)
                asm volatile("cp.async.cg.shared.global [%0], [%1], 16, %2;\n"
                             :: "r"(d + c * 16), "l"(gp + c * 8), "r"(vsz));
        }
        asm volatile("cp.async.commit_group;\n");
    }

    int us = 0, pf = GSTAGES - 1;
    for (int s = 0; s < NS; s++) {
        asm volatile("cp.async.wait_group %0;\n" :: "n"(GSTAGES - 2));
        __syncthreads();

        if (s + GSTAGES - 1 < NS) {
            unsigned d = sbase + (unsigned)(pf * STAGE_HALF * 2) + dRowOff;
            const __half* gp = gRow + (s + GSTAGES - 1) * 64;
            #pragma unroll
            for (int c = 0; c < 8; c++)
                asm volatile("cp.async.cg.shared.global [%0], [%1], 16, %2;\n"
                             :: "r"(d + c * 16), "l"(gp + c * 8), "r"(vsz));
        }
        asm volatile("cp.async.commit_group;\n");

        const unsigned stb = sbase + (unsigned)(us * STAGE_HALF * 2);

        #pragma unroll
        for (int kk = 0; kk < 64; kk += 16) {
            unsigned af[4][4], bf[4][2];
            #pragma unroll
            for (int mt = 0; mt < 4; mt++) {
                asm volatile(
                    "ldmatrix.sync.aligned.m8n8.x4.shared.b16 {%0,%1,%2,%3}, [%4];"
                    : "=r"(af[mt][0]), "=r"(af[mt][1]), "=r"(af[mt][2]), "=r"(af[mt][3])
                    : "r"(stb + aoff_lm[mt] + kk * 2));
            }
            #pragma unroll
            for (int p = 0; p < 2; p++) {
                asm volatile(
                    "ldmatrix.sync.aligned.m8n8.x4.shared.b16 {%0,%1,%2,%3}, [%4];"
                    : "=r"(bf[2*p][0]), "=r"(bf[2*p][1]),
                      "=r"(bf[2*p+1][0]), "=r"(bf[2*p+1][1])
                    : "r"(stb + boff_lm[p] + kk * 2));
            }
            #pragma unroll
            for (int mt = 0; mt < 4; mt++)
                #pragma unroll
                for (int nt = 0; nt < 4; nt++) {
                    float* c = acc[mt * 4 + nt];
                    asm volatile(
                        "mma.sync.aligned.m16n8k16.row.col.f32.f16.f16.f32 "
                        "{%0,%1,%2,%3}, {%4,%5,%6,%7}, {%8,%9}, {%0,%1,%2,%3};\n"
                        : "+f"(c[0]), "+f"(c[1]), "+f"(c[2]), "+f"(c[3])
                        : "r"(af[mt][0]), "r"(af[mt][1]), "r"(af[mt][2]), "r"(af[mt][3]),
                          "r"(bf[nt][0]), "r"(bf[nt][1]));
                }
        }
        if (++us == GSTAGES) us = 0;
        if (++pf == GSTAGES) pf = 0;
    }

    float*   outF = (float*)outv;
    __half2* outH = (__half2*)outv;
    const int erow = lane >> 2;
    const int ecol = (lane & 3) * 2;
    #pragma unroll
    for (int mt = 0; mt < 4; mt++) {
        #pragma unroll
        for (int nt = 0; nt < 4; nt++) {
            const float* c = acc[mt * 4 + nt];
            int col = bn + wn + nt * 8 + ecol;
            if (col >= colLim) continue;
            float bv0 = bias[col], bv1 = bias[col + 1];
            #pragma unroll
            for (int half = 0; half < 2; half++) {
                int row = bm + wm + mt * 16 + erow + half * 8;
                if (row < M) {
                    size_t off = ooff + (size_t)row * outStride + col;
                    float v0 = c[half * 2 + 0] + bv0;
                    float v1 = c[half * 2 + 1] + bv1;
                    if (MODE == 1) {
                        v0 = v0 / (1.f + expf(-1.702f * v0));
                        v1 = v1 / (1.f + expf(-1.702f * v1));
                        outH[off >> 1] = __floats2half2_rn(v0, v1);
                    } else if (MODE == 3) {
                        outH[off >> 1] = __floats2half2_rn(v0, v1);
                    } else {
                        if (MODE == 2) {
                            v0 += res[off];
                            v1 += res[off + 1];
                        }
                        outF[off]     = v0;
                        outF[off + 1] = v1;
                    }
                }
            }
        }
    }
}

// ---------------- spatial softmax: scale + rel-pos bias + normalize --------
__global__ void softmax_kernel(const float* __restrict__ rpb_s) {
    int wid = threadIdx.x >> 5, lane = threadIdx.x & 31;
    int q = blockIdx.x * 4 + wid;
    if (q >= LS) return;
    int b = blockIdx.y, h = blockIdx.z;
    size_t sbase = ((size_t)(b * 16 + h) * LS + q) * SKP;
    size_t pbase = ((size_t)(b * 16 + h) * LS + q) * PKP;
    int qi = 0, qj = 0;
    if (q > 0) { qi = (q - 1) / SS; qj = (q - 1) % SS; }
    float sv[7];
    float mx = -1e30f;
    #pragma unroll
    for (int it = 0; it < 7; it++) {
        int k = lane + it * 32;
        float s = -1e30f;
        if (k < LS) {
            s = g_S[sbase + k] * 0.125f;
            if (q > 0 && k > 0) {
                int ki = (k - 1) / SS, kj = (k - 1) % SS;
                int idx = (qi - ki + SS - 1) * (2 * SS - 1) + (qj - kj + SS - 1);
                s += rpb_s[idx * NH + h];
            }
        }
        sv[it] = s;
        mx = fmaxf(mx, s);
    }
    for (int m = 16; m; m >>= 1) mx = fmaxf(mx, __shfl_xor_sync(~0u, mx, m));
    float sum = 0.f;
    #pragma unroll
    for (int it = 0; it < 7; it++) {
        float p = (sv[it] > -1e29f) ? expf(sv[it] - mx) : 0.f;
        sv[it] = p; sum += p;
    }
    for (int m = 16; m; m >>= 1) sum += __shfl_xor_sync(~0u, sum, m);
    float inv = 1.f / sum;
    #pragma unroll
    for (int it = 0; it < 7; it++) {
        int k = lane + it * 32;
        if (k < LS) g_P[pbase + k] = __float2half_rn(sv[it] * inv);
    }
    for (int k = LS + lane; k < PKP; k += 32)
        g_P[pbase + k] = __ushort_as_half(0);
}

// ---------------- V transpose: Vt[bh][d][key] fp16, key-padded -------------
__global__ void vt_kernel() {
    __shared__ unsigned vsm[LS * 33];
    int z = blockIdx.x;
    int b = z >> 4, h = z & 15;
    int tid = threadIdx.x;
    for (int idx = tid; idx < LS * 32; idx += 256) {
        int ls = idx >> 5, dp = idx & 31;
        vsm[ls * 33 + dp] = *(const unsigned*)
            (g_QKVh + ((size_t)(ls * SB + b)) * 3072 + 2048 + h * 64 + dp * 2);
    }
    __syncthreads();
    const __half* vh = (const __half*)vsm;
    __half2* dst = (__half2*)(g_Vt + (size_t)z * HD * PKP);
    for (int idx = tid; idx < HD * (PKP / 2); idx += 256) {
        int d = idx / (PKP / 2), kp = idx % (PKP / 2);
        __half h0 = (2 * kp     < LS) ? vh[(2 * kp)     * 66 + d] : __ushort_as_half(0);
        __half h1 = (2 * kp + 1 < LS) ? vh[(2 * kp + 1) * 66 + d] : __ushort_as_half(0);
        dst[(size_t)d * (PKP / 2) + kp] = __halves2half2(h0, h1);
    }
}

// ---------------- Temporal attention: batch (n,l), seq T=8 -----------------
__global__ void temporal_attn_kernel(const float* __restrict__ rpb_t) {
    int bid = blockIdx.x;
    int h = bid & 15;
    int nl = bid >> 4;
    int n = nl & 7;
    int l = nl >> 3;
    __shared__ float Q[TT][HD + 1], K[TT][HD + 1], V[TT][HD + 1], P[TT][TT];
    int d = threadIdx.x;
    #pragma unroll
    for (int t = 0; t < TT; t++) {
        size_t r = (size_t)((l * TT + t) * NB + n);
        const __half* q = g_QKVh + r * 3072 + h * HD + d;
        Q[t][d] = __half2float(q[0]) * 0.125f;
        K[t][d] = __half2float(q[1024]);
        V[t][d] = __half2float(q[2048]);
    }
    __syncthreads();
    int tq = d >> 3, tk = d & 7;
    float s = rpb_t[(tq - tk + TT - 1) * NH + h];
    #pragma unroll
    for (int k = 0; k < HD; k++) s += Q[tq][k] * K[tk][k];
    float m = s;
    for (int msk = 4; msk; msk >>= 1) m = fmaxf(m, __shfl_xor_sync(~0u, m, msk));
    float p = expf(s - m);
    float sum = p;
    for (int msk = 4; msk; msk >>= 1) sum += __shfl_xor_sync(~0u, sum, msk);
    P[tq][tk] = p / sum;
    __syncthreads();
    #pragma unroll
    for (int t = 0; t < TT; t++) {
        float o = 0.f;
        #pragma unroll
        for (int k = 0; k < TT; k++) o += P[t][k] * V[k][d];
        g_ATTh[((size_t)((l * TT + t) * NB + n)) * CC + h * HD + d] = __float2half_rn(o);
    }
}

// ---------------------------------------------------------------------------
extern "C" void kernel_launch(void* const* d_in, const int* in_sizes, int n_in,
                              void* d_out, int out_size) {
    const float* x      = (const float*)d_in[0];
    const float* pos_w  = (const float*)d_in[1];
    const float* pos_b  = (const float*)d_in[2];
    const float* ln_t_g = (const float*)d_in[3];
    const float* ln_t_b = (const float*)d_in[4];
    const float* rpb_t  = (const float*)d_in[5];
    const float* wqkv_t = (const float*)d_in[6];
    const float* bqkv_t = (const float*)d_in[7];
    const float* wo_t   = (const float*)d_in[8];
    const float* bo_t   = (const float*)d_in[9];
    const float* ln1_g  = (const float*)d_in[10];
    const float* ln1_b  = (const float*)d_in[11];
    const float* rpb_s  = (const float*)d_in[12];
    const float* wqkv_s = (const float*)d_in[13];
    const float* bqkv_s = (const float*)d_in[14];
    const float* wo_s   = (const float*)d_in[15];
    const float* bo_s   = (const float*)d_in[16];
    const float* ln2_g  = (const float*)d_in[17];
    const float* ln2_b  = (const float*)d_in[18];
    const float* fc_w   = (const float*)d_in[19];
    const float* fc_b   = (const float*)d_in[20];
    const float* proj_w = (const float*)d_in[21];
    const float* proj_b = (const float*)d_in[22];
    float* out = (float*)d_out;

    float *pX, *pPROJ, *pXT, *pS, *pZERO;
    __half *pLNh, *pQKVh, *pATTh, *pHh, *pWTh, *pP, *pVt;
    cudaGetSymbolAddress((void**)&pX,    g_XBUF);
    cudaGetSymbolAddress((void**)&pLNh,  g_LNh);
    cudaGetSymbolAddress((void**)&pQKVh, g_QKVh);
    cudaGetSymbolAddress((void**)&pATTh, g_ATTh);
    cudaGetSymbolAddress((void**)&pPROJ, g_PROJ);
    cudaGetSymbolAddress((void**)&pXT,   g_XT);
    cudaGetSymbolAddress((void**)&pHh,   g_Hh);
    cudaGetSymbolAddress((void**)&pWTh,  g_WTh);
    cudaGetSymbolAddress((void**)&pS,    g_S);
    cudaGetSymbolAddress((void**)&pP,    g_P);
    cudaGetSymbolAddress((void**)&pVt,   g_Vt);
    cudaGetSymbolAddress((void**)&pZERO, g_ZERO);

    #define SET_SMEM(k) cudaFuncSetAttribute(k, \
        cudaFuncAttributeMaxDynamicSharedMemorySize, GSMEM_BYTES)
    SET_SMEM((tgemm_kernel<0,0>)); SET_SMEM((tgemm_kernel<1,0>));
    SET_SMEM((tgemm_kernel<2,0>)); SET_SMEM((tgemm_kernel<3,0>));
    SET_SMEM((tgemm_kernel<0,1>)); SET_SMEM((tgemm_kernel<3,2>));

    // fp16 weight copies (contiguous arena; one merged prep launch)
    __half* wqkvT = pWTh;
    __half* woT   = pWTh + 3145728;
    __half* wqkvS = pWTh + 4194304;
    __half* woS   = pWTh + 7340032;
    __half* fcW   = pWTh + 8388608;
    __half* projW = pWTh + 12582912;
    W6 ws;
    ws.p[0] = wqkv_t; ws.p[1] = wo_t; ws.p[2] = wqkv_s;
    ws.p[3] = wo_s;   ws.p[4] = fc_w; ws.p[5] = proj_w;
    wprep_all_kernel<<<16384, 256>>>(ws, pWTh);

    // Stage 1+LN_t fused: conv pos embed -> XBUF, LN_t -> LNh
    pos_ln_kernel<<<dim3(LL, NB), 256>>>(x, pos_w, pos_b, ln_t_g, ln_t_b);

    // Stage 2: temporal attention on patch rows -> xt_full (fp32) in pXT
    tgemm_kernel<3,0><<<dim3(24, 98, 1), 256, GSMEM_BYTES>>>(
        pLNh, 1024, wqkvT, 1024, bqkv_t, nullptr, pQKVh, 3072,
        PROWS, 3072, 1024, 3072);
    temporal_attn_kernel<<<LL * NB * NH, 64>>>(rpb_t);
    tgemm_kernel<2,0><<<dim3(8, 98, 1), 256, GSMEM_BYTES>>>(
        pATTh, 1024, woT, 1024, bo_t, pX + (size_t)NB * CC, pXT, 1024,
        PROWS, 1024, 1024, 1024);

    // Stage 3: spatial attention (seq 197 incl. cls) via batched GEMMs
    ln_kernel<<<SROWS, 256>>>(pXT, pX, pLNh, ln1_g, ln1_b, 1, 0);
    tgemm_kernel<3,0><<<dim3(24, 99, 1), 256, GSMEM_BYTES>>>(
        pLNh, 1024, wqkvS, 1024, bqkv_s, nullptr, pQKVh, 3072,
        SROWS, 3072, 1024, 3072);
    tgemm_kernel<0,1><<<dim3(2, 2, BH), 256, GSMEM_BYTES>>>(
        pQKVh, (size_t)SB * 3072, pQKVh + 1024, (size_t)SB * 3072,
        pZERO, nullptr, pS, SKP, LS, LS, 64, 198);
    softmax_kernel<<<dim3((LS + 3) / 4, SB, NH), 128>>>(rpb_s);
    vt_kernel<<<BH, 256>>>();
    tgemm_kernel<3,2><<<dim3(1, 2, BH), 256, GSMEM_BYTES>>>(
        pP, PKP, pVt, PKP, pZERO, nullptr, pATTh, (size_t)SB * 1024,
        LS, HD, PKP, HD);
    tgemm_kernel<0,0><<<dim3(8, 99, 1), 256, GSMEM_BYTES>>>(
        pATTh, 1024, woS, 1024, bo_s, nullptr, pPROJ, 1024,
        SROWS, 1024, 1024, 1024);

    // fused: spatial residual (+cls mean) into XBUF, then LN2 -> LNh
    resid_ln_kernel<<<ROWS, 256>>>(ln2_g, ln2_b);

    // Stage 4: MLP with QuickGELU (hidden in fp16)
    tgemm_kernel<1,0><<<dim3(32, 99, 1), 256, GSMEM_BYTES>>>(
        pLNh, 1024, fcW, 1024, fc_b, nullptr, pHh, 4096,
        ROWS, 4096, 1024, 4096);
    tgemm_kernel<2,0><<<dim3(8, 99, 1), 256, GSMEM_BYTES>>>(
        pHh, 4096, projW, 4096, proj_b, pX, out, 1024,
        ROWS, 1024, 4096, 1024);
}

// round 15
// speedup vs baseline: 1.0403x; 1.0403x over previous
#include <cuda_runtime.h>
#include <cuda_fp16.h>
#include <math.h>
#include <stdint.h>

#define TT 8
#define SS 14
#define LL 196            // S*S
#define NB 8
#define CC 1024
#define NH 16
#define HD 64
#define NTOK (1 + LL*TT)  // 1569
#define ROWS (NTOK*NB)    // 12552
#define PROWS (LL*TT*NB)  // 12544 patch rows
#define LS (LL + 1)       // 197 spatial seq
#define SB (TT*NB)        // 64 spatial batch
#define SROWS (LS*SB)     // 12608
#define BH   1024         // SB*NH spatial batch*heads
#define SKP 200           // S row pad (floats)
#define PKP 256           // P/Vt key pad (halves)

// ---------------- scratch (device globals; no allocations) ----------------
__device__ __align__(256) float  g_XBUF[(size_t)ROWS * CC];      // residual stream
__device__ __align__(256) __half g_LNh [(size_t)SROWS * CC];     // LN out (fp16)
__device__ __align__(256) __half g_QKVh[(size_t)SROWS * 3 * CC]; // qkv fp16
__device__ __align__(256) __half g_ATTh[(size_t)SROWS * CC];     // attn out (fp16)
__device__ __align__(256) float  g_PROJ[(size_t)SROWS * CC];     // spatial proj out
__device__ __align__(256) float  g_XT  [(size_t)PROWS * CC];     // xt_full fp32
__device__ __align__(256) __half g_Hh  [(size_t)ROWS * 4 * CC];  // MLP hidden (fp16)
__device__ __align__(256) __half g_WTh [16777216];               // fp16 weights
__device__ __align__(256) float  g_S   [(size_t)BH * LS * SKP];  // spatial scores fp32
__device__ __align__(256) __half g_P   [(size_t)BH * LS * PKP];  // probs fp16 (padded)
__device__ __align__(256) __half g_Vt  [(size_t)BH * HD * PKP];  // V^T fp16 (padded)
__device__ float g_ZERO[256];                                    // zero bias

// ---------------- merged weight prep: fp32 -> fp16 (all 6 tensors) --------
struct W6 { const float* p[6]; };
__global__ void wprep_all_kernel(W6 ws, __half* __restrict__ d) {
    const int cum1 = 786432, cum2 = 1048576, cum3 = 1835008,
              cum4 = 2097152, cum5 = 3145728, cum6 = 4194304;
    int i = blockIdx.x * 256 + threadIdx.x;
    if (i >= cum6) return;
    int s; int base;
    if      (i < cum1) { s = 0; base = 0; }
    else if (i < cum2) { s = 1; base = cum1; }
    else if (i < cum3) { s = 2; base = cum2; }
    else if (i < cum4) { s = 3; base = cum3; }
    else if (i < cum5) { s = 4; base = cum4; }
    else               { s = 5; base = cum5; }
    float4 v = ((const float4*)ws.p[s])[i - base];
    ((__half2*)d)[i * 2]     = __floats2half2_rn(v.x, v.y);
    ((__half2*)d)[i * 2 + 1] = __floats2half2_rn(v.z, v.w);
}

// ---------------- Stage 1 fused: depthwise conv pos-embed + LayerNorm_t ----
__global__ void __launch_bounds__(256)
pos_ln_kernel(const float* __restrict__ x, const float* __restrict__ pw,
              const float* __restrict__ pb,
              const float* __restrict__ g, const float* __restrict__ b) {
    __shared__ float rows[TT][CC];
    __shared__ float reds[8][TT], reds2[8][TT];
    __shared__ float stat[TT][2];
    int l = blockIdx.x, n = blockIdx.y, tid = threadIdx.x;
    int i = l / SS, j = l % SS;
    int wid = tid >> 5, lane = tid & 31;
    float s[TT], s2[TT];
    #pragma unroll
    for (int t = 0; t < TT; t++) { s[t] = 0.f; s2[t] = 0.f; }

    if (l == 0) {
        for (int c = tid; c < CC; c += 256)
            g_XBUF[(size_t)n * CC + c] = x[(size_t)n * CC + c];
    }

    for (int ci = 0; ci < 4; ci++) {
        int c = ci * 256 + tid;
        float w[27];
        #pragma unroll
        for (int k = 0; k < 27; k++) w[k] = pw[(size_t)c * 27 + k];
        float acc[TT], xown[TT];
        #pragma unroll
        for (int t = 0; t < TT; t++) acc[t] = pb[c];
        #pragma unroll
        for (int di = 0; di < 3; di++) {
            int i2 = i + di - 1;
            if ((unsigned)i2 >= SS) continue;
            #pragma unroll
            for (int dj = 0; dj < 3; dj++) {
                int j2 = j + dj - 1;
                if ((unsigned)j2 >= SS) continue;
                int kidx = di * 3 + dj;
                const float* base = x + ((size_t)(1 + (i2 * SS + j2) * TT) * NB + n) * CC + c;
                bool cen = (di == 1 && dj == 1);
                #pragma unroll
                for (int t2 = 0; t2 < TT; t2++) {
                    float val = base[(size_t)t2 * NB * CC];
                    if (cen) xown[t2] = val;
                    if (t2 + 1 < TT) acc[t2 + 1] += w[kidx]      * val;
                    acc[t2]                      += w[9  + kidx] * val;
                    if (t2 > 0)      acc[t2 - 1] += w[18 + kidx] * val;
                }
            }
        }
        #pragma unroll
        for (int t = 0; t < TT; t++) {
            float v = xown[t] + acc[t];
            g_XBUF[((size_t)((1 + l * TT + t) * NB) + n) * CC + c] = v;
            rows[t][c] = v;
            s[t] += v; s2[t] += v * v;
        }
    }
    #pragma unroll
    for (int t = 0; t < TT; t++)
        for (int m = 16; m; m >>= 1) {
            s[t]  += __shfl_xor_sync(~0u, s[t],  m);
            s2[t] += __shfl_xor_sync(~0u, s2[t], m);
        }
    if (lane == 0) {
        #pragma unroll
        for (int t = 0; t < TT; t++) { reds[wid][t] = s[t]; reds2[wid][t] = s2[t]; }
    }
    __syncthreads();
    if (lane < 8) {
        float a = reds[lane][wid], a2 = reds2[lane][wid];
        #pragma unroll
        for (int m = 4; m; m >>= 1) {
            a  += __shfl_xor_sync(0xffu, a,  m);
            a2 += __shfl_xor_sync(0xffu, a2, m);
        }
        if (lane == 0) {
            float mean = a * (1.f / CC);
            float var  = a2 * (1.f / CC) - mean * mean;
            stat[wid][0] = mean;
            stat[wid][1] = rsqrtf(var + 1e-5f);
        }
    }
    __syncthreads();
    for (int ci = 0; ci < 4; ci++) {
        int c = ci * 256 + tid;
        float gc = g[c], bc = b[c];
        #pragma unroll
        for (int t = 0; t < TT; t++) {
            float v = rows[t][c];
            g_LNh[((size_t)((l * TT + t) * NB) + n) * CC + c] =
                __float2half_rn((v - stat[t][0]) * stat[t][1] * gc + bc);
        }
    }
}

// ---------------- LayerNorm (mode 1: spatial gather) -> fp16 ---------------
__global__ void ln_kernel(const float* __restrict__ src,
                          const float* __restrict__ srcCls,
                          __half* __restrict__ dst,
                          const float* __restrict__ g, const float* __restrict__ b,
                          int mode, int srcOff) {
    int row = blockIdx.x;
    const float* xr;
    if (mode == 0) {
        xr = src + (size_t)(row + srcOff) * CC;
    } else {
        int ls = row / SB, bb = row % SB;
        int t = bb / NB, n = bb % NB;
        if (ls == 0) xr = srcCls + (size_t)n * CC;
        else         xr = src + (size_t)(((ls - 1) * TT + t) * NB + n) * CC;
    }
    int tid = threadIdx.x;
    float s = 0.f, s2 = 0.f;
    float v[4];
    #pragma unroll
    for (int it = 0; it < 4; it++) {
        float val = xr[tid + it * 256];
        v[it] = val; s += val; s2 += val * val;
    }
    __shared__ float red[2][8];
    for (int m = 16; m; m >>= 1) {
        s  += __shfl_xor_sync(~0u, s, m);
        s2 += __shfl_xor_sync(~0u, s2, m);
    }
    if ((tid & 31) == 0) { red[0][tid >> 5] = s; red[1][tid >> 5] = s2; }
    __syncthreads();
    s = 0.f; s2 = 0.f;
    #pragma unroll
    for (int w = 0; w < 8; w++) { s += red[0][w]; s2 += red[1][w]; }
    float mean = s * (1.f / CC);
    float var  = s2 * (1.f / CC) - mean * mean;
    float inv  = rsqrtf(var + 1e-5f);
    __half* dr = dst + (size_t)row * CC;
    #pragma unroll
    for (int it = 0; it < 4; it++) {
        int c = tid + it * 256;
        dr[c] = __float2half_rn((v[it] - mean) * inv * g[c] + b[c]);
    }
}

// ---------------- fused spatial residual + LayerNorm2 ----------------------
__global__ void resid_ln_kernel(const float* __restrict__ g,
                                const float* __restrict__ b) {
    int row = blockIdx.x, tid = threadIdx.x;
    int token = row >> 3, n = row & 7;
    float v[4];
    float s = 0.f, s2 = 0.f;
    #pragma unroll
    for (int it = 0; it < 4; it++) {
        int c = tid + it * 256;
        float base = g_XBUF[(size_t)row * CC + c];
        float add;
        if (token == 0) {
            float a = 0.f;
            #pragma unroll
            for (int t = 0; t < TT; t++)
                a += g_PROJ[((size_t)(t * NB + n)) * CC + c];
            add = a * 0.125f;
        } else {
            int p = token - 1;
            int l = p >> 3, t = p & 7;
            add = g_PROJ[((size_t)((l + 1) * SB + t * NB + n)) * CC + c];
        }
        float vv = base + add;
        g_XBUF[(size_t)row * CC + c] = vv;
        v[it] = vv; s += vv; s2 += vv * vv;
    }
    __shared__ float red[2][8];
    for (int m = 16; m; m >>= 1) {
        s  += __shfl_xor_sync(~0u, s, m);
        s2 += __shfl_xor_sync(~0u, s2, m);
    }
    if ((tid & 31) == 0) { red[0][tid >> 5] = s; red[1][tid >> 5] = s2; }
    __syncthreads();
    s = 0.f; s2 = 0.f;
    #pragma unroll
    for (int w = 0; w < 8; w++) { s += red[0][w]; s2 += red[1][w]; }
    float mean = s * (1.f / CC);
    float var  = s2 * (1.f / CC) - mean * mean;
    float inv  = rsqrtf(var + 1e-5f);
    __half* dr = g_LNh + (size_t)row * CC;
    #pragma unroll
    for (int it = 0; it < 4; it++) {
        int c = tid + it * 256;
        dr[c] = __float2half_rn((v[it] - mean) * inv * g[c] + b[c]);
    }
}

// ---------------- fp16 tensor-core GEMM, cp.async + ldmatrix, BK=32 --------
// C[M,N] = A[M,K] @ B[N,K]^T + bias (+epilogue). Strided rows, batched.
// MODE 0: fp32 store | 1: QuickGELU->fp16 | 2: residual add fp32 | 3: fp16 store
// BATCH 0: none | 1: qkv-layout A/B (scores), S-out | 2: P/Vt in, qkv-scatter out
// 128x128 tile, BK=32 halves, 5 smem stages (3 slabs of prefetch in flight).
#define HSTR 40
#define STAGE_HALF (2 * 128 * HSTR)            // 10240 halves = 20480 B
#define GSTAGES 5
#define GSMEM_BYTES (GSTAGES * STAGE_HALF * 2) // 102400

template<int MODE, int BATCH>
__global__ void __launch_bounds__(256, 2)
tgemm_kernel(const __half* __restrict__ A, size_t strideA,
             const __half* __restrict__ B, size_t strideB,
             const float* __restrict__ bias, const float* __restrict__ res,
             void* __restrict__ outv, size_t outStride,
             int M, int N, int K, int colLim) {
    extern __shared__ __half smh[];
    const int tid  = threadIdx.x;
    const int bm   = blockIdx.y * 128, bn = blockIdx.x * 128;
    const int z    = blockIdx.z;
    const int lane = tid & 31, wid = tid >> 5;
    const int wm   = (wid & 1) << 6;
    const int wn   = (wid >> 1) << 5;

    size_t aoff = 0, boff = 0, ooff = 0;
    if (BATCH == 1) {
        size_t e = (size_t)(z >> 4) * 3072 + (size_t)(z & 15) * 64;
        aoff = e; boff = e;
        ooff = (size_t)z * LS * SKP;
    } else if (BATCH == 2) {
        aoff = (size_t)z * LS * PKP;
        boff = (size_t)z * HD * PKP;
        ooff = (size_t)(z >> 4) * 1024 + (size_t)(z & 15) * 64;
    }

    const int  lrow  = tid & 127;
    const bool loadA = tid < 128;
    int  growi = loadA ? (bm + lrow) : (bn + lrow);
    const bool valid = loadA ? (growi < M) : (growi < N);
    const int  vsz   = valid ? 16 : 0;
    if (!valid) growi = 0;
    const __half* gRow = (loadA ? (A + aoff) : (B + boff))
                       + (size_t)growi * (loadA ? strideA : strideB);
    unsigned sbase = (unsigned)__cvta_generic_to_shared(smh);
    const unsigned dRowOff = (loadA ? 0u : 128u * HSTR * 2) + lrow * (HSTR * 2);

    // ldmatrix per-lane byte offsets (within a stage)
    unsigned aoff_lm[4], boff_lm[2];
    #pragma unroll
    for (int mt = 0; mt < 4; mt++)
        aoff_lm[mt] = (unsigned)(((wm + mt * 16 + (lane & 15)) * HSTR
                                  + ((lane >> 4) << 3)) * 2);
    #pragma unroll
    for (int p = 0; p < 2; p++)
        boff_lm[p] = (unsigned)(((128 + wn + (2 * p + (lane >> 4)) * 8 + (lane & 7)) * HSTR
                                 + (((lane >> 3) & 1) << 3)) * 2);

    float acc[16][4];
    #pragma unroll
    for (int i = 0; i < 16; i++)
        #pragma unroll
        for (int j = 0; j < 4; j++) acc[i][j] = 0.f;

    const int NS = K >> 5;   // 32 halves per slab

    // prologue: fill stages 0..GSTAGES-2
    #pragma unroll
    for (int s = 0; s < GSTAGES - 1; s++) {
        if (s < NS) {
            unsigned d = sbase + (unsigned)(s * STAGE_HALF * 2) + dRowOff;
            const __half* gp = gRow + s * 32;
            #pragma unroll
            for (int c = 0; c < 4; c++)
                asm volatile("cp.async.cg.shared.global [%0], [%1], 16, %2;\n"
                             :: "r"(d + c * 16), "l"(gp + c * 8), "r"(vsz));
        }
        asm volatile("cp.async.commit_group;\n");
    }

    int us = 0, pf = GSTAGES - 1;
    for (int s = 0; s < NS; s++) {
        asm volatile("cp.async.wait_group %0;\n" :: "n"(GSTAGES - 2));
        __syncthreads();

        if (s + GSTAGES - 1 < NS) {
            unsigned d = sbase + (unsigned)(pf * STAGE_HALF * 2) + dRowOff;
            const __half* gp = gRow + (s + GSTAGES - 1) * 32;
            #pragma unroll
            for (int c = 0; c < 4; c++)
                asm volatile("cp.async.cg.shared.global [%0], [%1], 16, %2;\n"
                             :: "r"(d + c * 16), "l"(gp + c * 8), "r"(vsz));
        }
        asm volatile("cp.async.commit_group;\n");

        const unsigned stb = sbase + (unsigned)(us * STAGE_HALF * 2);

        #pragma unroll
        for (int kk = 0; kk < 32; kk += 16) {
            unsigned af[4][4], bf[4][2];
            #pragma unroll
            for (int mt = 0; mt < 4; mt++) {
                asm volatile(
                    "ldmatrix.sync.aligned.m8n8.x4.shared.b16 {%0,%1,%2,%3}, [%4];"
                    : "=r"(af[mt][0]), "=r"(af[mt][1]), "=r"(af[mt][2]), "=r"(af[mt][3])
                    : "r"(stb + aoff_lm[mt] + kk * 2));
            }
            #pragma unroll
            for (int p = 0; p < 2; p++) {
                asm volatile(
                    "ldmatrix.sync.aligned.m8n8.x4.shared.b16 {%0,%1,%2,%3}, [%4];"
                    : "=r"(bf[2*p][0]), "=r"(bf[2*p][1]),
                      "=r"(bf[2*p+1][0]), "=r"(bf[2*p+1][1])
                    : "r"(stb + boff_lm[p] + kk * 2));
            }
            #pragma unroll
            for (int mt = 0; mt < 4; mt++)
                #pragma unroll
                for (int nt = 0; nt < 4; nt++) {
                    float* c = acc[mt * 4 + nt];
                    asm volatile(
                        "mma.sync.aligned.m16n8k16.row.col.f32.f16.f16.f32 "
                        "{%0,%1,%2,%3}, {%4,%5,%6,%7}, {%8,%9}, {%0,%1,%2,%3};\n"
                        : "+f"(c[0]), "+f"(c[1]), "+f"(c[2]), "+f"(c[3])
                        : "r"(af[mt][0]), "r"(af[mt][1]), "r"(af[mt][2]), "r"(af[mt][3]),
                          "r"(bf[nt][0]), "r"(bf[nt][1]));
                }
        }
        if (++us == GSTAGES) us = 0;
        if (++pf == GSTAGES) pf = 0;
    }

    float*   outF = (float*)outv;
    __half2* outH = (__half2*)outv;
    const int erow = lane >> 2;
    const int ecol = (lane & 3) * 2;
    #pragma unroll
    for (int mt = 0; mt < 4; mt++) {
        #pragma unroll
        for (int nt = 0; nt < 4; nt++) {
            const float* c = acc[mt * 4 + nt];
            int col = bn + wn + nt * 8 + ecol;
            if (col >= colLim) continue;
            float bv0 = bias[col], bv1 = bias[col + 1];
            #pragma unroll
            for (int half = 0; half < 2; half++) {
                int row = bm + wm + mt * 16 + erow + half * 8;
                if (row < M) {
                    size_t off = ooff + (size_t)row * outStride + col;
                    float v0 = c[half * 2 + 0] + bv0;
                    float v1 = c[half * 2 + 1] + bv1;
                    if (MODE == 1) {
                        v0 = v0 / (1.f + expf(-1.702f * v0));
                        v1 = v1 / (1.f + expf(-1.702f * v1));
                        outH[off >> 1] = __floats2half2_rn(v0, v1);
                    } else if (MODE == 3) {
                        outH[off >> 1] = __floats2half2_rn(v0, v1);
                    } else {
                        if (MODE == 2) {
                            v0 += res[off];
                            v1 += res[off + 1];
                        }
                        outF[off]     = v0;
                        outF[off + 1] = v1;
                    }
                }
            }
        }
    }
}

// ---------------- spatial softmax: scale + rel-pos bias + normalize --------
__global__ void softmax_kernel(const float* __restrict__ rpb_s) {
    int wid = threadIdx.x >> 5, lane = threadIdx.x & 31;
    int q = blockIdx.x * 4 + wid;
    if (q >= LS) return;
    int b = blockIdx.y, h = blockIdx.z;
    size_t sbase = ((size_t)(b * 16 + h) * LS + q) * SKP;
    size_t pbase = ((size_t)(b * 16 + h) * LS + q) * PKP;
    int qi = 0, qj = 0;
    if (q > 0) { qi = (q - 1) / SS; qj = (q - 1) % SS; }
    float sv[7];
    float mx = -1e30f;
    #pragma unroll
    for (int it = 0; it < 7; it++) {
        int k = lane + it * 32;
        float s = -1e30f;
        if (k < LS) {
            s = g_S[sbase + k] * 0.125f;
            if (q > 0 && k > 0) {
                int ki = (k - 1) / SS, kj = (k - 1) % SS;
                int idx = (qi - ki + SS - 1) * (2 * SS - 1) + (qj - kj + SS - 1);
                s += rpb_s[idx * NH + h];
            }
        }
        sv[it] = s;
        mx = fmaxf(mx, s);
    }
    for (int m = 16; m; m >>= 1) mx = fmaxf(mx, __shfl_xor_sync(~0u, mx, m));
    float sum = 0.f;
    #pragma unroll
    for (int it = 0; it < 7; it++) {
        float p = (sv[it] > -1e29f) ? expf(sv[it] - mx) : 0.f;
        sv[it] = p; sum += p;
    }
    for (int m = 16; m; m >>= 1) sum += __shfl_xor_sync(~0u, sum, m);
    float inv = 1.f / sum;
    #pragma unroll
    for (int it = 0; it < 7; it++) {
        int k = lane + it * 32;
        if (k < LS) g_P[pbase + k] = __float2half_rn(sv[it] * inv);
    }
    for (int k = LS + lane; k < PKP; k += 32)
        g_P[pbase + k] = __ushort_as_half(0);
}

// ---------------- V transpose: Vt[bh][d][key] fp16, key-padded -------------
__global__ void vt_kernel() {
    __shared__ unsigned vsm[LS * 33];
    int z = blockIdx.x;
    int b = z >> 4, h = z & 15;
    int tid = threadIdx.x;
    for (int idx = tid; idx < LS * 32; idx += 256) {
        int ls = idx >> 5, dp = idx & 31;
        vsm[ls * 33 + dp] = *(const unsigned*)
            (g_QKVh + ((size_t)(ls * SB + b)) * 3072 + 2048 + h * 64 + dp * 2);
    }
    __syncthreads();
    const __half* vh = (const __half*)vsm;
    __half2* dst = (__half2*)(g_Vt + (size_t)z * HD * PKP);
    for (int idx = tid; idx < HD * (PKP / 2); idx += 256) {
        int d = idx / (PKP / 2), kp = idx % (PKP / 2);
        __half h0 = (2 * kp     < LS) ? vh[(2 * kp)     * 66 + d] : __ushort_as_half(0);
        __half h1 = (2 * kp + 1 < LS) ? vh[(2 * kp + 1) * 66 + d] : __ushort_as_half(0);
        dst[(size_t)d * (PKP / 2) + kp] = __halves2half2(h0, h1);
    }
}

// ---------------- Temporal attention: batch (n,l), seq T=8 -----------------
__global__ void temporal_attn_kernel(const float* __restrict__ rpb_t) {
    int bid = blockIdx.x;
    int h = bid & 15;
    int nl = bid >> 4;
    int n = nl & 7;
    int l = nl >> 3;
    __shared__ float Q[TT][HD + 1], K[TT][HD + 1], V[TT][HD + 1], P[TT][TT];
    int d = threadIdx.x;
    #pragma unroll
    for (int t = 0; t < TT; t++) {
        size_t r = (size_t)((l * TT + t) * NB + n);
        const __half* q = g_QKVh + r * 3072 + h * HD + d;
        Q[t][d] = __half2float(q[0]) * 0.125f;
        K[t][d] = __half2float(q[1024]);
        V[t][d] = __half2float(q[2048]);
    }
    __syncthreads();
    int tq = d >> 3, tk = d & 7;
    float s = rpb_t[(tq - tk + TT - 1) * NH + h];
    #pragma unroll
    for (int k = 0; k < HD; k++) s += Q[tq][k] * K[tk][k];
    float m = s;
    for (int msk = 4; msk; msk >>= 1) m = fmaxf(m, __shfl_xor_sync(~0u, m, msk));
    float p = expf(s - m);
    float sum = p;
    for (int msk = 4; msk; msk >>= 1) sum += __shfl_xor_sync(~0u, sum, msk);
    P[tq][tk] = p / sum;
    __syncthreads();
    #pragma unroll
    for (int t = 0; t < TT; t++) {
        float o = 0.f;
        #pragma unroll
        for (int k = 0; k < TT; k++) o += P[t][k] * V[k][d];
        g_ATTh[((size_t)((l * TT + t) * NB + n)) * CC + h * HD + d] = __float2half_rn(o);
    }
}

// ---------------------------------------------------------------------------
extern "C" void kernel_launch(void* const* d_in, const int* in_sizes, int n_in,
                              void* d_out, int out_size) {
    const float* x      = (const float*)d_in[0];
    const float* pos_w  = (const float*)d_in[1];
    const float* pos_b  = (const float*)d_in[2];
    const float* ln_t_g = (const float*)d_in[3];
    const float* ln_t_b = (const float*)d_in[4];
    const float* rpb_t  = (const float*)d_in[5];
    const float* wqkv_t = (const float*)d_in[6];
    const float* bqkv_t = (const float*)d_in[7];
    const float* wo_t   = (const float*)d_in[8];
    const float* bo_t   = (const float*)d_in[9];
    const float* ln1_g  = (const float*)d_in[10];
    const float* ln1_b  = (const float*)d_in[11];
    const float* rpb_s  = (const float*)d_in[12];
    const float* wqkv_s = (const float*)d_in[13];
    const float* bqkv_s = (const float*)d_in[14];
    const float* wo_s   = (const float*)d_in[15];
    const float* bo_s   = (const float*)d_in[16];
    const float* ln2_g  = (const float*)d_in[17];
    const float* ln2_b  = (const float*)d_in[18];
    const float* fc_w   = (const float*)d_in[19];
    const float* fc_b   = (const float*)d_in[20];
    const float* proj_w = (const float*)d_in[21];
    const float* proj_b = (const float*)d_in[22];
    float* out = (float*)d_out;

    float *pX, *pPROJ, *pXT, *pS, *pZERO;
    __half *pLNh, *pQKVh, *pATTh, *pHh, *pWTh, *pP, *pVt;
    cudaGetSymbolAddress((void**)&pX,    g_XBUF);
    cudaGetSymbolAddress((void**)&pLNh,  g_LNh);
    cudaGetSymbolAddress((void**)&pQKVh, g_QKVh);
    cudaGetSymbolAddress((void**)&pATTh, g_ATTh);
    cudaGetSymbolAddress((void**)&pPROJ, g_PROJ);
    cudaGetSymbolAddress((void**)&pXT,   g_XT);
    cudaGetSymbolAddress((void**)&pHh,   g_Hh);
    cudaGetSymbolAddress((void**)&pWTh,  g_WTh);
    cudaGetSymbolAddress((void**)&pS,    g_S);
    cudaGetSymbolAddress((void**)&pP,    g_P);
    cudaGetSymbolAddress((void**)&pVt,   g_Vt);
    cudaGetSymbolAddress((void**)&pZERO, g_ZERO);

    #define SET_SMEM(k) cudaFuncSetAttribute(k, \
        cudaFuncAttributeMaxDynamicSharedMemorySize, GSMEM_BYTES)
    SET_SMEM((tgemm_kernel<0,0>)); SET_SMEM((tgemm_kernel<1,0>));
    SET_SMEM((tgemm_kernel<2,0>)); SET_SMEM((tgemm_kernel<3,0>));
    SET_SMEM((tgemm_kernel<0,1>)); SET_SMEM((tgemm_kernel<3,2>));

    // fp16 weight copies (contiguous arena; one merged prep launch)
    __half* wqkvT = pWTh;
    __half* woT   = pWTh + 3145728;
    __half* wqkvS = pWTh + 4194304;
    __half* woS   = pWTh + 7340032;
    __half* fcW   = pWTh + 8388608;
    __half* projW = pWTh + 12582912;
    W6 ws;
    ws.p[0] = wqkv_t; ws.p[1] = wo_t; ws.p[2] = wqkv_s;
    ws.p[3] = wo_s;   ws.p[4] = fc_w; ws.p[5] = proj_w;
    wprep_all_kernel<<<16384, 256>>>(ws, pWTh);

    // Stage 1+LN_t fused: conv pos embed -> XBUF, LN_t -> LNh
    pos_ln_kernel<<<dim3(LL, NB), 256>>>(x, pos_w, pos_b, ln_t_g, ln_t_b);

    // Stage 2: temporal attention on patch rows -> xt_full (fp32) in pXT
    tgemm_kernel<3,0><<<dim3(24, 98, 1), 256, GSMEM_BYTES>>>(
        pLNh, 1024, wqkvT, 1024, bqkv_t, nullptr, pQKVh, 3072,
        PROWS, 3072, 1024, 3072);
    temporal_attn_kernel<<<LL * NB * NH, 64>>>(rpb_t);
    tgemm_kernel<2,0><<<dim3(8, 98, 1), 256, GSMEM_BYTES>>>(
        pATTh, 1024, woT, 1024, bo_t, pX + (size_t)NB * CC, pXT, 1024,
        PROWS, 1024, 1024, 1024);

    // Stage 3: spatial attention (seq 197 incl. cls) via batched GEMMs
    ln_kernel<<<SROWS, 256>>>(pXT, pX, pLNh, ln1_g, ln1_b, 1, 0);
    tgemm_kernel<3,0><<<dim3(24, 99, 1), 256, GSMEM_BYTES>>>(
        pLNh, 1024, wqkvS, 1024, bqkv_s, nullptr, pQKVh, 3072,
        SROWS, 3072, 1024, 3072);
    tgemm_kernel<0,1><<<dim3(2, 2, BH), 256, GSMEM_BYTES>>>(
        pQKVh, (size_t)SB * 3072, pQKVh + 1024, (size_t)SB * 3072,
        pZERO, nullptr, pS, SKP, LS, LS, 64, 198);
    softmax_kernel<<<dim3((LS + 3) / 4, SB, NH), 128>>>(rpb_s);
    vt_kernel<<<BH, 256>>>();
    tgemm_kernel<3,2><<<dim3(1, 2, BH), 256, GSMEM_BYTES>>>(
        pP, PKP, pVt, PKP, pZERO, nullptr, pATTh, (size_t)SB * 1024,
        LS, HD, PKP, HD);
    tgemm_kernel<0,0><<<dim3(8, 99, 1), 256, GSMEM_BYTES>>>(
        pATTh, 1024, woS, 1024, bo_s, nullptr, pPROJ, 1024,
        SROWS, 1024, 1024, 1024);

    // fused: spatial residual (+cls mean) into XBUF, then LN2 -> LNh
    resid_ln_kernel<<<ROWS, 256>>>(ln2_g, ln2_b);

    // Stage 4: MLP with QuickGELU (hidden in fp16)
    tgemm_kernel<1,0><<<dim3(32, 99, 1), 256, GSMEM_BYTES>>>(
        pLNh, 1024, fcW, 1024, fc_b, nullptr, pHh, 4096,
        ROWS, 4096, 1024, 4096);
    tgemm_kernel<2,0><<<dim3(8, 99, 1), 256, GSMEM_BYTES>>>(
        pHh, 4096, projW, 4096, proj_b, pX, out, 1024,
        ROWS, 1024, 4096, 1024);
}

// round 16
// speedup vs baseline: 1.0598x; 1.0188x over previous
#include <cuda_runtime.h>
#include <cuda_fp16.h>
#include <math.h>
#include <stdint.h>

#define TT 8
#define SS 14
#define LL 196            // S*S
#define NB 8
#define CC 1024
#define NH 16
#define HD 64
#define NTOK (1 + LL*TT)  // 1569
#define ROWS (NTOK*NB)    // 12552
#define PROWS (LL*TT*NB)  // 12544 patch rows
#define LS (LL + 1)       // 197 spatial seq
#define SB (TT*NB)        // 64 spatial batch
#define SROWS (LS*SB)     // 12608
#define BH   1024         // SB*NH spatial batch*heads
#define SKP 200           // S row pad (floats)
#define PKP 224           // P/Vt key pad (halves, mult of 32)

// ---------------- scratch (device globals; no allocations) ----------------
__device__ __align__(256) float  g_XBUF[(size_t)ROWS * CC];      // residual stream
__device__ __align__(256) __half g_LNh [(size_t)SROWS * CC];     // LN out (fp16)
__device__ __align__(256) __half g_QKVh[(size_t)SROWS * 3 * CC]; // qkv fp16
__device__ __align__(256) __half g_ATTh[(size_t)SROWS * CC];     // attn out (fp16)
__device__ __align__(256) float  g_PROJ[(size_t)SROWS * CC];     // spatial proj out
__device__ __align__(256) float  g_XT  [(size_t)PROWS * CC];     // xt_full fp32
__device__ __align__(256) __half g_Hh  [(size_t)ROWS * 4 * CC];  // MLP hidden (fp16)
__device__ __align__(256) __half g_WTh [16777216];               // fp16 weights
__device__ __align__(256) float  g_S   [(size_t)BH * LS * SKP];  // spatial scores fp32
__device__ __align__(256) __half g_P   [(size_t)BH * LS * PKP];  // probs fp16 (padded)
__device__ __align__(256) __half g_Vt  [(size_t)BH * HD * PKP];  // V^T fp16 (padded)
__device__ float g_ZERO[256];                                    // zero bias

// ---------------- merged weight prep: fp32 -> fp16 (all 6 tensors) --------
struct W6 { const float* p[6]; };
__global__ void wprep_all_kernel(W6 ws, __half* __restrict__ d) {
    const int cum1 = 786432, cum2 = 1048576, cum3 = 1835008,
              cum4 = 2097152, cum5 = 3145728, cum6 = 4194304;
    int i = blockIdx.x * 256 + threadIdx.x;
    if (i >= cum6) return;
    int s; int base;
    if      (i < cum1) { s = 0; base = 0; }
    else if (i < cum2) { s = 1; base = cum1; }
    else if (i < cum3) { s = 2; base = cum2; }
    else if (i < cum4) { s = 3; base = cum3; }
    else if (i < cum5) { s = 4; base = cum4; }
    else               { s = 5; base = cum5; }
    float4 v = ((const float4*)ws.p[s])[i - base];
    ((__half2*)d)[i * 2]     = __floats2half2_rn(v.x, v.y);
    ((__half2*)d)[i * 2 + 1] = __floats2half2_rn(v.z, v.w);
}

// ---------------- Stage 1 fused: depthwise conv pos-embed + LayerNorm_t ----
__global__ void __launch_bounds__(256)
pos_ln_kernel(const float* __restrict__ x, const float* __restrict__ pw,
              const float* __restrict__ pb,
              const float* __restrict__ g, const float* __restrict__ b) {
    __shared__ float rows[TT][CC];
    __shared__ float reds[8][TT], reds2[8][TT];
    __shared__ float stat[TT][2];
    int l = blockIdx.x, n = blockIdx.y, tid = threadIdx.x;
    int i = l / SS, j = l % SS;
    int wid = tid >> 5, lane = tid & 31;
    float s[TT], s2[TT];
    #pragma unroll
    for (int t = 0; t < TT; t++) { s[t] = 0.f; s2[t] = 0.f; }

    if (l == 0) {
        for (int c = tid; c < CC; c += 256)
            g_XBUF[(size_t)n * CC + c] = x[(size_t)n * CC + c];
    }

    for (int ci = 0; ci < 4; ci++) {
        int c = ci * 256 + tid;
        float w[27];
        #pragma unroll
        for (int k = 0; k < 27; k++) w[k] = pw[(size_t)c * 27 + k];
        float acc[TT], xown[TT];
        #pragma unroll
        for (int t = 0; t < TT; t++) acc[t] = pb[c];
        #pragma unroll
        for (int di = 0; di < 3; di++) {
            int i2 = i + di - 1;
            if ((unsigned)i2 >= SS) continue;
            #pragma unroll
            for (int dj = 0; dj < 3; dj++) {
                int j2 = j + dj - 1;
                if ((unsigned)j2 >= SS) continue;
                int kidx = di * 3 + dj;
                const float* base = x + ((size_t)(1 + (i2 * SS + j2) * TT) * NB + n) * CC + c;
                bool cen = (di == 1 && dj == 1);
                #pragma unroll
                for (int t2 = 0; t2 < TT; t2++) {
                    float val = base[(size_t)t2 * NB * CC];
                    if (cen) xown[t2] = val;
                    if (t2 + 1 < TT) acc[t2 + 1] += w[kidx]      * val;
                    acc[t2]                      += w[9  + kidx] * val;
                    if (t2 > 0)      acc[t2 - 1] += w[18 + kidx] * val;
                }
            }
        }
        #pragma unroll
        for (int t = 0; t < TT; t++) {
            float v = xown[t] + acc[t];
            g_XBUF[((size_t)((1 + l * TT + t) * NB) + n) * CC + c] = v;
            rows[t][c] = v;
            s[t] += v; s2[t] += v * v;
        }
    }
    #pragma unroll
    for (int t = 0; t < TT; t++)
        for (int m = 16; m; m >>= 1) {
            s[t]  += __shfl_xor_sync(~0u, s[t],  m);
            s2[t] += __shfl_xor_sync(~0u, s2[t], m);
        }
    if (lane == 0) {
        #pragma unroll
        for (int t = 0; t < TT; t++) { reds[wid][t] = s[t]; reds2[wid][t] = s2[t]; }
    }
    __syncthreads();
    if (lane < 8) {
        float a = reds[lane][wid], a2 = reds2[lane][wid];
        #pragma unroll
        for (int m = 4; m; m >>= 1) {
            a  += __shfl_xor_sync(0xffu, a,  m);
            a2 += __shfl_xor_sync(0xffu, a2, m);
        }
        if (lane == 0) {
            float mean = a * (1.f / CC);
            float var  = a2 * (1.f / CC) - mean * mean;
            stat[wid][0] = mean;
            stat[wid][1] = rsqrtf(var + 1e-5f);
        }
    }
    __syncthreads();
    for (int ci = 0; ci < 4; ci++) {
        int c = ci * 256 + tid;
        float gc = g[c], bc = b[c];
        #pragma unroll
        for (int t = 0; t < TT; t++) {
            float v = rows[t][c];
            g_LNh[((size_t)((l * TT + t) * NB) + n) * CC + c] =
                __float2half_rn((v - stat[t][0]) * stat[t][1] * gc + bc);
        }
    }
}

// ---------------- LayerNorm (mode 1: spatial gather) -> fp16 ---------------
__global__ void ln_kernel(const float* __restrict__ src,
                          const float* __restrict__ srcCls,
                          __half* __restrict__ dst,
                          const float* __restrict__ g, const float* __restrict__ b,
                          int mode, int srcOff) {
    int row = blockIdx.x;
    const float* xr;
    if (mode == 0) {
        xr = src + (size_t)(row + srcOff) * CC;
    } else {
        int ls = row / SB, bb = row % SB;
        int t = bb / NB, n = bb % NB;
        if (ls == 0) xr = srcCls + (size_t)n * CC;
        else         xr = src + (size_t)(((ls - 1) * TT + t) * NB + n) * CC;
    }
    int tid = threadIdx.x;
    float s = 0.f, s2 = 0.f;
    float v[4];
    #pragma unroll
    for (int it = 0; it < 4; it++) {
        float val = xr[tid + it * 256];
        v[it] = val; s += val; s2 += val * val;
    }
    __shared__ float red[2][8];
    for (int m = 16; m; m >>= 1) {
        s  += __shfl_xor_sync(~0u, s, m);
        s2 += __shfl_xor_sync(~0u, s2, m);
    }
    if ((tid & 31) == 0) { red[0][tid >> 5] = s; red[1][tid >> 5] = s2; }
    __syncthreads();
    s = 0.f; s2 = 0.f;
    #pragma unroll
    for (int w = 0; w < 8; w++) { s += red[0][w]; s2 += red[1][w]; }
    float mean = s * (1.f / CC);
    float var  = s2 * (1.f / CC) - mean * mean;
    float inv  = rsqrtf(var + 1e-5f);
    __half* dr = dst + (size_t)row * CC;
    #pragma unroll
    for (int it = 0; it < 4; it++) {
        int c = tid + it * 256;
        dr[c] = __float2half_rn((v[it] - mean) * inv * g[c] + b[c]);
    }
}

// ---------------- fused spatial residual + LayerNorm2 ----------------------
__global__ void resid_ln_kernel(const float* __restrict__ g,
                                const float* __restrict__ b) {
    int row = blockIdx.x, tid = threadIdx.x;
    int token = row >> 3, n = row & 7;
    float v[4];
    float s = 0.f, s2 = 0.f;
    #pragma unroll
    for (int it = 0; it < 4; it++) {
        int c = tid + it * 256;
        float base = g_XBUF[(size_t)row * CC + c];
        float add;
        if (token == 0) {
            float a = 0.f;
            #pragma unroll
            for (int t = 0; t < TT; t++)
                a += g_PROJ[((size_t)(t * NB + n)) * CC + c];
            add = a * 0.125f;
        } else {
            int p = token - 1;
            int l = p >> 3, t = p & 7;
            add = g_PROJ[((size_t)((l + 1) * SB + t * NB + n)) * CC + c];
        }
        float vv = base + add;
        g_XBUF[(size_t)row * CC + c] = vv;
        v[it] = vv; s += vv; s2 += vv * vv;
    }
    __shared__ float red[2][8];
    for (int m = 16; m; m >>= 1) {
        s  += __shfl_xor_sync(~0u, s, m);
        s2 += __shfl_xor_sync(~0u, s2, m);
    }
    if ((tid & 31) == 0) { red[0][tid >> 5] = s; red[1][tid >> 5] = s2; }
    __syncthreads();
    s = 0.f; s2 = 0.f;
    #pragma unroll
    for (int w = 0; w < 8; w++) { s += red[0][w]; s2 += red[1][w]; }
    float mean = s * (1.f / CC);
    float var  = s2 * (1.f / CC) - mean * mean;
    float inv  = rsqrtf(var + 1e-5f);
    __half* dr = g_LNh + (size_t)row * CC;
    #pragma unroll
    for (int it = 0; it < 4; it++) {
        int c = tid + it * 256;
        dr[c] = __float2half_rn((v[it] - mean) * inv * g[c] + b[c]);
    }
}

// ---------------- fp16 tensor-core GEMM, cp.async + ldmatrix, BK=32 --------
// (R13-proven config: 4 stages, power-of-2 masks.)
// C[M,N] = A[M,K] @ B[N,K]^T + bias (+epilogue). Strided rows, batched.
// MODE 0: fp32 store | 1: QuickGELU->fp16 | 2: residual add fp32 | 3: fp16 store
// BATCH 0: none | 1: qkv-layout A/B (scores), S-out | 2: P/Vt in, qkv-scatter out
#define HSTR 40
#define STAGE_HALF (2 * 128 * HSTR)
#define GSTAGES 4
#define GSMEM_BYTES (GSTAGES * STAGE_HALF * 2)  // 81920

template<int MODE, int BATCH>
__global__ void __launch_bounds__(256, 2)
tgemm_kernel(const __half* __restrict__ A, size_t strideA,
             const __half* __restrict__ B, size_t strideB,
             const float* __restrict__ bias, const float* __restrict__ res,
             void* __restrict__ outv, size_t outStride,
             int M, int N, int K, int colLim) {
    extern __shared__ __half smh[];
    const int tid  = threadIdx.x;
    const int bm   = blockIdx.y * 128, bn = blockIdx.x * 128;
    const int z    = blockIdx.z;
    const int lane = tid & 31, wid = tid >> 5;
    const int wm   = (wid & 1) << 6;
    const int wn   = (wid >> 1) << 5;

    size_t aoff = 0, boff = 0, ooff = 0;
    if (BATCH == 1) {
        size_t e = (size_t)(z >> 4) * 3072 + (size_t)(z & 15) * 64;
        aoff = e; boff = e;
        ooff = (size_t)z * LS * SKP;
    } else if (BATCH == 2) {
        aoff = (size_t)z * LS * PKP;
        boff = (size_t)z * HD * PKP;
        ooff = (size_t)(z >> 4) * 1024 + (size_t)(z & 15) * 64;
    }

    const int  lrow  = tid & 127;
    const bool loadA = tid < 128;
    int  growi = loadA ? (bm + lrow) : (bn + lrow);
    const bool valid = loadA ? (growi < M) : (growi < N);
    const int  vsz   = valid ? 16 : 0;
    if (!valid) growi = 0;
    const __half* gRow = (loadA ? (A + aoff) : (B + boff))
                       + (size_t)growi * (loadA ? strideA : strideB);
    unsigned sbase = (unsigned)__cvta_generic_to_shared(smh);
    const unsigned dRowOff = (loadA ? 0u : 128u * HSTR * 2) + lrow * (HSTR * 2);

    // ldmatrix per-lane byte offsets (within a stage)
    unsigned aoff_lm[4], boff_lm[2];
    #pragma unroll
    for (int mt = 0; mt < 4; mt++)
        aoff_lm[mt] = (unsigned)(((wm + mt * 16 + (lane & 15)) * HSTR
                                  + ((lane >> 4) << 3)) * 2);
    #pragma unroll
    for (int p = 0; p < 2; p++)
        boff_lm[p] = (unsigned)(((128 + wn + (2 * p + (lane >> 4)) * 8 + (lane & 7)) * HSTR
                                 + (((lane >> 3) & 1) << 3)) * 2);

    float acc[16][4];
    #pragma unroll
    for (int i = 0; i < 16; i++)
        #pragma unroll
        for (int j = 0; j < 4; j++) acc[i][j] = 0.f;

    const int NS = K >> 5;

    #pragma unroll
    for (int s = 0; s < GSTAGES - 1; s++) {
        if (s < NS) {
            unsigned d = sbase + (unsigned)(s * STAGE_HALF * 2) + dRowOff;
            const __half* gp = gRow + s * 32;
            #pragma unroll
            for (int c = 0; c < 4; c++)
                asm volatile("cp.async.cg.shared.global [%0], [%1], 16, %2;\n"
                             :: "r"(d + c * 16), "l"(gp + c * 8), "r"(vsz));
        }
        asm volatile("cp.async.commit_group;\n");
    }

    for (int s = 0; s < NS; s++) {
        asm volatile("cp.async.wait_group %0;\n" :: "n"(GSTAGES - 2));
        __syncthreads();

        if (s + GSTAGES - 1 < NS) {
            int st = (s + GSTAGES - 1) & (GSTAGES - 1);
            unsigned d = sbase + (unsigned)(st * STAGE_HALF * 2) + dRowOff;
            const __half* gp = gRow + (s + GSTAGES - 1) * 32;
            #pragma unroll
            for (int c = 0; c < 4; c++)
                asm volatile("cp.async.cg.shared.global [%0], [%1], 16, %2;\n"
                             :: "r"(d + c * 16), "l"(gp + c * 8), "r"(vsz));
        }
        asm volatile("cp.async.commit_group;\n");

        const unsigned stb = sbase + (unsigned)((s & (GSTAGES - 1)) * STAGE_HALF * 2);

        #pragma unroll
        for (int kk = 0; kk < 32; kk += 16) {
            unsigned af[4][4], bf[4][2];
            #pragma unroll
            for (int mt = 0; mt < 4; mt++) {
                asm volatile(
                    "ldmatrix.sync.aligned.m8n8.x4.shared.b16 {%0,%1,%2,%3}, [%4];"
                    : "=r"(af[mt][0]), "=r"(af[mt][1]), "=r"(af[mt][2]), "=r"(af[mt][3])
                    : "r"(stb + aoff_lm[mt] + kk * 2));
            }
            #pragma unroll
            for (int p = 0; p < 2; p++) {
                asm volatile(
                    "ldmatrix.sync.aligned.m8n8.x4.shared.b16 {%0,%1,%2,%3}, [%4];"
                    : "=r"(bf[2*p][0]), "=r"(bf[2*p][1]),
                      "=r"(bf[2*p+1][0]), "=r"(bf[2*p+1][1])
                    : "r"(stb + boff_lm[p] + kk * 2));
            }
            #pragma unroll
            for (int mt = 0; mt < 4; mt++)
                #pragma unroll
                for (int nt = 0; nt < 4; nt++) {
                    float* c = acc[mt * 4 + nt];
                    asm volatile(
                        "mma.sync.aligned.m16n8k16.row.col.f32.f16.f16.f32 "
                        "{%0,%1,%2,%3}, {%4,%5,%6,%7}, {%8,%9}, {%0,%1,%2,%3};\n"
                        : "+f"(c[0]), "+f"(c[1]), "+f"(c[2]), "+f"(c[3])
                        : "r"(af[mt][0]), "r"(af[mt][1]), "r"(af[mt][2]), "r"(af[mt][3]),
                          "r"(bf[nt][0]), "r"(bf[nt][1]));
                }
        }
    }

    float*   outF = (float*)outv;
    __half2* outH = (__half2*)outv;
    const int erow = lane >> 2;
    const int ecol = (lane & 3) * 2;
    #pragma unroll
    for (int mt = 0; mt < 4; mt++) {
        #pragma unroll
        for (int nt = 0; nt < 4; nt++) {
            const float* c = acc[mt * 4 + nt];
            int col = bn + wn + nt * 8 + ecol;
            if (col >= colLim) continue;
            float bv0 = bias[col], bv1 = bias[col + 1];
            #pragma unroll
            for (int half = 0; half < 2; half++) {
                int row = bm + wm + mt * 16 + erow + half * 8;
                if (row < M) {
                    size_t off = ooff + (size_t)row * outStride + col;
                    float v0 = c[half * 2 + 0] + bv0;
                    float v1 = c[half * 2 + 1] + bv1;
                    if (MODE == 1) {
                        v0 = v0 / (1.f + expf(-1.702f * v0));
                        v1 = v1 / (1.f + expf(-1.702f * v1));
                        outH[off >> 1] = __floats2half2_rn(v0, v1);
                    } else if (MODE == 3) {
                        outH[off >> 1] = __floats2half2_rn(v0, v1);
                    } else {
                        if (MODE == 2) {
                            v0 += res[off];
                            v1 += res[off + 1];
                        }
                        outF[off]     = v0;
                        outF[off + 1] = v1;
                    }
                }
            }
        }
    }
}

// ---------------- spatial softmax: scale + rel-pos bias + normalize --------
__global__ void softmax_kernel(const float* __restrict__ rpb_s) {
    int wid = threadIdx.x >> 5, lane = threadIdx.x & 31;
    int q = blockIdx.x * 4 + wid;
    if (q >= LS) return;
    int b = blockIdx.y, h = blockIdx.z;
    size_t sbase = ((size_t)(b * 16 + h) * LS + q) * SKP;
    size_t pbase = ((size_t)(b * 16 + h) * LS + q) * PKP;
    int qi = 0, qj = 0;
    if (q > 0) { qi = (q - 1) / SS; qj = (q - 1) % SS; }
    float sv[7];
    float mx = -1e30f;
    #pragma unroll
    for (int it = 0; it < 7; it++) {
        int k = lane + it * 32;
        float s = -1e30f;
        if (k < LS) {
            s = g_S[sbase + k] * 0.125f;
            if (q > 0 && k > 0) {
                int ki = (k - 1) / SS, kj = (k - 1) % SS;
                int idx = (qi - ki + SS - 1) * (2 * SS - 1) + (qj - kj + SS - 1);
                s += rpb_s[idx * NH + h];
            }
        }
        sv[it] = s;
        mx = fmaxf(mx, s);
    }
    for (int m = 16; m; m >>= 1) mx = fmaxf(mx, __shfl_xor_sync(~0u, mx, m));
    float sum = 0.f;
    #pragma unroll
    for (int it = 0; it < 7; it++) {
        float p = (sv[it] > -1e29f) ? expf(sv[it] - mx) : 0.f;
        sv[it] = p; sum += p;
    }
    for (int m = 16; m; m >>= 1) sum += __shfl_xor_sync(~0u, sum, m);
    float inv = 1.f / sum;
    #pragma unroll
    for (int it = 0; it < 7; it++) {
        int k = lane + it * 32;
        if (k < LS) g_P[pbase + k] = __float2half_rn(sv[it] * inv);
    }
    for (int k = LS + lane; k < PKP; k += 32)
        g_P[pbase + k] = __ushort_as_half(0);
}

// ---------------- V transpose: Vt[bh][d][key] fp16, key-padded -------------
__global__ void vt_kernel() {
    __shared__ unsigned vsm[LS * 33];
    int z = blockIdx.x;
    int b = z >> 4, h = z & 15;
    int tid = threadIdx.x;
    for (int idx = tid; idx < LS * 32; idx += 256) {
        int ls = idx >> 5, dp = idx & 31;
        vsm[ls * 33 + dp] = *(const unsigned*)
            (g_QKVh + ((size_t)(ls * SB + b)) * 3072 + 2048 + h * 64 + dp * 2);
    }
    __syncthreads();
    const __half* vh = (const __half*)vsm;
    __half2* dst = (__half2*)(g_Vt + (size_t)z * HD * PKP);
    for (int idx = tid; idx < HD * (PKP / 2); idx += 256) {
        int d = idx / (PKP / 2), kp = idx % (PKP / 2);
        __half h0 = (2 * kp     < LS) ? vh[(2 * kp)     * 66 + d] : __ushort_as_half(0);
        __half h1 = (2 * kp + 1 < LS) ? vh[(2 * kp + 1) * 66 + d] : __ushort_as_half(0);
        dst[(size_t)d * (PKP / 2) + kp] = __halves2half2(h0, h1);
    }
}

// ---------------- Temporal attention: block = (l,n), all 16 heads ----------
// QKV staged in smem via uint4 loads; per-warp 2 heads; half2 math/stores.
#define TSTR 3080   // halves per token row: 3072 + 8 pad (4-bank shift/row)
#define TATT_SMEM (TT * TSTR * 2)   // 49280 bytes (dynamic)
__global__ void __launch_bounds__(256)
temporal_attn_kernel(const float* __restrict__ rpb_t) {
    extern __shared__ __half sm[];
    __shared__ float Psm[NH][TT][TT];
    int bid = blockIdx.x;           // 0..1567
    int n = bid & 7, l = bid >> 3;
    int tid = threadIdx.x, wid = tid >> 5, lane = tid & 31;

    // stage 8 token rows (3072 halves each) with vectorized loads
    uint4* dsm = (uint4*)sm;        // TSTR/8 = 385 uint4 per row
    for (int idx = tid; idx < TT * 384; idx += 256) {
        int t = idx / 384, u = idx % 384;
        size_t r = (size_t)((l * TT + t) * NB + n);
        dsm[t * 385 + u] = ((const uint4*)(g_QKVh + r * 3072))[u];
    }
    __syncthreads();

    #pragma unroll
    for (int hh = 0; hh < 2; hh++) {
        int h = wid * 2 + hh;
        // scores: lane handles pairs (lane) and (lane+32); p -> tq=p>>3, tk=p&7
        float sv[2];
        #pragma unroll
        for (int pp = 0; pp < 2; pp++) {
            int p = lane + pp * 32;
            int tq = p >> 3, tk = p & 7;
            const __half2* qp = (const __half2*)(sm + tq * TSTR + h * HD);
            const __half2* kp = (const __half2*)(sm + tk * TSTR + 1024 + h * HD);
            float acc = 0.f;
            #pragma unroll
            for (int d2 = 0; d2 < 32; d2++) {
                float2 qv = __half22float2(qp[d2]);
                float2 kv = __half22float2(kp[d2]);
                acc += qv.x * kv.x + qv.y * kv.y;
            }
            sv[pp] = acc * 0.125f + rpb_t[(tq - tk + TT - 1) * NH + h];
        }
        // softmax per row (groups of 8 lanes share tq)
        #pragma unroll
        for (int pp = 0; pp < 2; pp++) {
            float m = sv[pp];
            for (int msk = 4; msk; msk >>= 1)
                m = fmaxf(m, __shfl_xor_sync(~0u, m, msk));
            float e = expf(sv[pp] - m);
            float su = e;
            for (int msk = 4; msk; msk >>= 1)
                su += __shfl_xor_sync(~0u, su, msk);
            sv[pp] = e / su;
        }
        Psm[h][lane >> 3][lane & 7]       = sv[0];
        Psm[h][4 + (lane >> 3)][lane & 7] = sv[1];
        __syncwarp();
        // output: lane = half2 index d2 (0..31)
        float2 o[TT];
        #pragma unroll
        for (int t = 0; t < TT; t++) { o[t].x = 0.f; o[t].y = 0.f; }
        #pragma unroll
        for (int k = 0; k < TT; k++) {
            float2 vv = __half22float2(
                *(const __half2*)(sm + k * TSTR + 2048 + h * HD + 2 * lane));
            #pragma unroll
            for (int t = 0; t < TT; t++) {
                float pkt = Psm[h][t][k];
                o[t].x += pkt * vv.x;
                o[t].y += pkt * vv.y;
            }
        }
        #pragma unroll
        for (int t = 0; t < TT; t++) {
            size_t r = (size_t)((l * TT + t) * NB + n);
            *(__half2*)(g_ATTh + r * CC + h * HD + 2 * lane) =
                __floats2half2_rn(o[t].x, o[t].y);
        }
        __syncwarp();
    }
}

// ---------------------------------------------------------------------------
extern "C" void kernel_launch(void* const* d_in, const int* in_sizes, int n_in,
                              void* d_out, int out_size) {
    const float* x      = (const float*)d_in[0];
    const float* pos_w  = (const float*)d_in[1];
    const float* pos_b  = (const float*)d_in[2];
    const float* ln_t_g = (const float*)d_in[3];
    const float* ln_t_b = (const float*)d_in[4];
    const float* rpb_t  = (const float*)d_in[5];
    const float* wqkv_t = (const float*)d_in[6];
    const float* bqkv_t = (const float*)d_in[7];
    const float* wo_t   = (const float*)d_in[8];
    const float* bo_t   = (const float*)d_in[9];
    const float* ln1_g  = (const float*)d_in[10];
    const float* ln1_b  = (const float*)d_in[11];
    const float* rpb_s  = (const float*)d_in[12];
    const float* wqkv_s = (const float*)d_in[13];
    const float* bqkv_s = (const float*)d_in[14];
    const float* wo_s   = (const float*)d_in[15];
    const float* bo_s   = (const float*)d_in[16];
    const float* ln2_g  = (const float*)d_in[17];
    const float* ln2_b  = (const float*)d_in[18];
    const float* fc_w   = (const float*)d_in[19];
    const float* fc_b   = (const float*)d_in[20];
    const float* proj_w = (const float*)d_in[21];
    const float* proj_b = (const float*)d_in[22];
    float* out = (float*)d_out;

    float *pX, *pPROJ, *pXT, *pS, *pZERO;
    __half *pLNh, *pQKVh, *pATTh, *pHh, *pWTh, *pP, *pVt;
    cudaGetSymbolAddress((void**)&pX,    g_XBUF);
    cudaGetSymbolAddress((void**)&pLNh,  g_LNh);
    cudaGetSymbolAddress((void**)&pQKVh, g_QKVh);
    cudaGetSymbolAddress((void**)&pATTh, g_ATTh);
    cudaGetSymbolAddress((void**)&pPROJ, g_PROJ);
    cudaGetSymbolAddress((void**)&pXT,   g_XT);
    cudaGetSymbolAddress((void**)&pHh,   g_Hh);
    cudaGetSymbolAddress((void**)&pWTh,  g_WTh);
    cudaGetSymbolAddress((void**)&pS,    g_S);
    cudaGetSymbolAddress((void**)&pP,    g_P);
    cudaGetSymbolAddress((void**)&pVt,   g_Vt);
    cudaGetSymbolAddress((void**)&pZERO, g_ZERO);

    #define SET_SMEM(k, sz) cudaFuncSetAttribute(k, \
        cudaFuncAttributeMaxDynamicSharedMemorySize, sz)
    SET_SMEM((tgemm_kernel<0,0>), GSMEM_BYTES);
    SET_SMEM((tgemm_kernel<1,0>), GSMEM_BYTES);
    SET_SMEM((tgemm_kernel<2,0>), GSMEM_BYTES);
    SET_SMEM((tgemm_kernel<3,0>), GSMEM_BYTES);
    SET_SMEM((tgemm_kernel<0,1>), GSMEM_BYTES);
    SET_SMEM((tgemm_kernel<3,2>), GSMEM_BYTES);
    SET_SMEM(temporal_attn_kernel, TATT_SMEM);

    // fp16 weight copies (contiguous arena; one merged prep launch)
    __half* wqkvT = pWTh;
    __half* woT   = pWTh + 3145728;
    __half* wqkvS = pWTh + 4194304;
    __half* woS   = pWTh + 7340032;
    __half* fcW   = pWTh + 8388608;
    __half* projW = pWTh + 12582912;
    W6 ws;
    ws.p[0] = wqkv_t; ws.p[1] = wo_t; ws.p[2] = wqkv_s;
    ws.p[3] = wo_s;   ws.p[4] = fc_w; ws.p[5] = proj_w;
    wprep_all_kernel<<<16384, 256>>>(ws, pWTh);

    // Stage 1+LN_t fused: conv pos embed -> XBUF, LN_t -> LNh
    pos_ln_kernel<<<dim3(LL, NB), 256>>>(x, pos_w, pos_b, ln_t_g, ln_t_b);

    // Stage 2: temporal attention on patch rows -> xt_full (fp32) in pXT
    tgemm_kernel<3,0><<<dim3(24, 98, 1), 256, GSMEM_BYTES>>>(
        pLNh, 1024, wqkvT, 1024, bqkv_t, nullptr, pQKVh, 3072,
        PROWS, 3072, 1024, 3072);
    temporal_attn_kernel<<<LL * NB, 256, TATT_SMEM>>>(rpb_t);
    tgemm_kernel<2,0><<<dim3(8, 98, 1), 256, GSMEM_BYTES>>>(
        pATTh, 1024, woT, 1024, bo_t, pX + (size_t)NB * CC, pXT, 1024,
        PROWS, 1024, 1024, 1024);

    // Stage 3: spatial attention (seq 197 incl. cls) via batched GEMMs
    ln_kernel<<<SROWS, 256>>>(pXT, pX, pLNh, ln1_g, ln1_b, 1, 0);
    tgemm_kernel<3,0><<<dim3(24, 99, 1), 256, GSMEM_BYTES>>>(
        pLNh, 1024, wqkvS, 1024, bqkv_s, nullptr, pQKVh, 3072,
        SROWS, 3072, 1024, 3072);
    tgemm_kernel<0,1><<<dim3(2, 2, BH), 256, GSMEM_BYTES>>>(
        pQKVh, (size_t)SB * 3072, pQKVh + 1024, (size_t)SB * 3072,
        pZERO, nullptr, pS, SKP, LS, LS, 64, 198);
    softmax_kernel<<<dim3((LS + 3) / 4, SB, NH), 128>>>(rpb_s);
    vt_kernel<<<BH, 256>>>();
    tgemm_kernel<3,2><<<dim3(1, 2, BH), 256, GSMEM_BYTES>>>(
        pP, PKP, pVt, PKP, pZERO, nullptr, pATTh, (size_t)SB * 1024,
        LS, HD, PKP, HD);
    tgemm_kernel<0,0><<<dim3(8, 99, 1), 256, GSMEM_BYTES>>>(
        pATTh, 1024, woS, 1024, bo_s, nullptr, pPROJ, 1024,
        SROWS, 1024, 1024, 1024);

    // fused: spatial residual (+cls mean) into XBUF, then LN2 -> LNh
    resid_ln_kernel<<<ROWS, 256>>>(ln2_g, ln2_b);

    // Stage 4: MLP with QuickGELU (hidden in fp16)
    tgemm_kernel<1,0><<<dim3(32, 99, 1), 256, GSMEM_BYTES>>>(
        pLNh, 1024, fcW, 1024, fc_b, nullptr, pHh, 4096,
        ROWS, 4096, 1024, 4096);
    tgemm_kernel<2,0><<<dim3(8, 99, 1), 256, GSMEM_BYTES>>>(
        pHh, 4096, projW, 4096, proj_b, pX, out, 1024,
        ROWS, 1024, 4096, 1024);
}

// round 17
// speedup vs baseline: 1.0722x; 1.0117x over previous
#include <cuda_runtime.h>
#include <cuda_fp16.h>
#include <math.h>
#include <stdint.h>

#define TT 8
#define SS 14
#define LL 196            // S*S
#define NB 8
#define CC 1024
#define NH 16
#define HD 64
#define NTOK (1 + LL*TT)  // 1569
#define ROWS (NTOK*NB)    // 12552
#define PROWS (LL*TT*NB)  // 12544 patch rows
#define LS (LL + 1)       // 197 spatial seq
#define SB (TT*NB)        // 64 spatial batch
#define SROWS (LS*SB)     // 12608
#define BH   1024         // SB*NH spatial batch*heads
#define SKP 200           // S row pad (floats)
#define PKP 224           // P/Vt key pad (halves, mult of 32)

// ---------------- scratch (device globals; no allocations) ----------------
__device__ __align__(256) float  g_XBUF[(size_t)ROWS * CC];      // residual stream
__device__ __align__(256) __half g_LNh [(size_t)SROWS * CC];     // LN out (fp16)
__device__ __align__(256) __half g_QKVh[(size_t)SROWS * 3 * CC]; // qkv fp16
__device__ __align__(256) __half g_ATTh[(size_t)SROWS * CC];     // attn out (fp16)
__device__ __align__(256) float  g_PROJ[(size_t)SROWS * CC];     // spatial proj out
__device__ __align__(256) float  g_XT  [(size_t)PROWS * CC];     // xt_full fp32
__device__ __align__(256) __half g_Hh  [(size_t)ROWS * 4 * CC];  // MLP hidden (fp16)
__device__ __align__(256) __half g_WTh [16777216];               // fp16 weights
__device__ __align__(256) float  g_S   [(size_t)BH * LS * SKP];  // spatial scores fp32
__device__ __align__(256) __half g_P   [(size_t)BH * LS * PKP];  // probs fp16 (padded)
__device__ __align__(256) __half g_Vt  [(size_t)BH * HD * PKP];  // V^T fp16 (padded)
__device__ float g_ZERO[256];                                    // zero bias

// packed ex2: two half exponents at once (1 MUFU per pair)
__device__ __forceinline__ __half2 h2ex2(__half2 y) {
    unsigned out, in = *(unsigned*)&y;
    asm("ex2.approx.f16x2 %0, %1;" : "=r"(out) : "r"(in));
    return *(__half2*)&out;
}

// ---------------- merged weight prep: fp32 -> fp16 (all 6 tensors) --------
struct W6 { const float* p[6]; };
__global__ void wprep_all_kernel(W6 ws, __half* __restrict__ d) {
    const int cum1 = 786432, cum2 = 1048576, cum3 = 1835008,
              cum4 = 2097152, cum5 = 3145728, cum6 = 4194304;
    int i = blockIdx.x * 256 + threadIdx.x;
    if (i >= cum6) return;
    int s; int base;
    if      (i < cum1) { s = 0; base = 0; }
    else if (i < cum2) { s = 1; base = cum1; }
    else if (i < cum3) { s = 2; base = cum2; }
    else if (i < cum4) { s = 3; base = cum3; }
    else if (i < cum5) { s = 4; base = cum4; }
    else               { s = 5; base = cum5; }
    float4 v = ((const float4*)ws.p[s])[i - base];
    ((__half2*)d)[i * 2]     = __floats2half2_rn(v.x, v.y);
    ((__half2*)d)[i * 2 + 1] = __floats2half2_rn(v.z, v.w);
}

// ---------------- Stage 1 fused: depthwise conv pos-embed + LayerNorm_t ----
__global__ void __launch_bounds__(256)
pos_ln_kernel(const float* __restrict__ x, const float* __restrict__ pw,
              const float* __restrict__ pb,
              const float* __restrict__ g, const float* __restrict__ b) {
    __shared__ float rows[TT][CC];
    __shared__ float reds[8][TT], reds2[8][TT];
    __shared__ float stat[TT][2];
    int l = blockIdx.x, n = blockIdx.y, tid = threadIdx.x;
    int i = l / SS, j = l % SS;
    int wid = tid >> 5, lane = tid & 31;
    float s[TT], s2[TT];
    #pragma unroll
    for (int t = 0; t < TT; t++) { s[t] = 0.f; s2[t] = 0.f; }

    if (l == 0) {
        for (int c = tid; c < CC; c += 256)
            g_XBUF[(size_t)n * CC + c] = x[(size_t)n * CC + c];
    }

    for (int ci = 0; ci < 4; ci++) {
        int c = ci * 256 + tid;
        float w[27];
        #pragma unroll
        for (int k = 0; k < 27; k++) w[k] = pw[(size_t)c * 27 + k];
        float acc[TT], xown[TT];
        #pragma unroll
        for (int t = 0; t < TT; t++) acc[t] = pb[c];
        #pragma unroll
        for (int di = 0; di < 3; di++) {
            int i2 = i + di - 1;
            if ((unsigned)i2 >= SS) continue;
            #pragma unroll
            for (int dj = 0; dj < 3; dj++) {
                int j2 = j + dj - 1;
                if ((unsigned)j2 >= SS) continue;
                int kidx = di * 3 + dj;
                const float* base = x + ((size_t)(1 + (i2 * SS + j2) * TT) * NB + n) * CC + c;
                bool cen = (di == 1 && dj == 1);
                #pragma unroll
                for (int t2 = 0; t2 < TT; t2++) {
                    float val = base[(size_t)t2 * NB * CC];
                    if (cen) xown[t2] = val;
                    if (t2 + 1 < TT) acc[t2 + 1] += w[kidx]      * val;
                    acc[t2]                      += w[9  + kidx] * val;
                    if (t2 > 0)      acc[t2 - 1] += w[18 + kidx] * val;
                }
            }
        }
        #pragma unroll
        for (int t = 0; t < TT; t++) {
            float v = xown[t] + acc[t];
            g_XBUF[((size_t)((1 + l * TT + t) * NB) + n) * CC + c] = v;
            rows[t][c] = v;
            s[t] += v; s2[t] += v * v;
        }
    }
    #pragma unroll
    for (int t = 0; t < TT; t++)
        for (int m = 16; m; m >>= 1) {
            s[t]  += __shfl_xor_sync(~0u, s[t],  m);
            s2[t] += __shfl_xor_sync(~0u, s2[t], m);
        }
    if (lane == 0) {
        #pragma unroll
        for (int t = 0; t < TT; t++) { reds[wid][t] = s[t]; reds2[wid][t] = s2[t]; }
    }
    __syncthreads();
    if (lane < 8) {
        float a = reds[lane][wid], a2 = reds2[lane][wid];
        #pragma unroll
        for (int m = 4; m; m >>= 1) {
            a  += __shfl_xor_sync(0xffu, a,  m);
            a2 += __shfl_xor_sync(0xffu, a2, m);
        }
        if (lane == 0) {
            float mean = a * (1.f / CC);
            float var  = a2 * (1.f / CC) - mean * mean;
            stat[wid][0] = mean;
            stat[wid][1] = rsqrtf(var + 1e-5f);
        }
    }
    __syncthreads();
    for (int ci = 0; ci < 4; ci++) {
        int c = ci * 256 + tid;
        float gc = g[c], bc = b[c];
        #pragma unroll
        for (int t = 0; t < TT; t++) {
            float v = rows[t][c];
            g_LNh[((size_t)((l * TT + t) * NB) + n) * CC + c] =
                __float2half_rn((v - stat[t][0]) * stat[t][1] * gc + bc);
        }
    }
}

// ---------------- LayerNorm (mode 1: spatial gather) -> fp16 ---------------
__global__ void ln_kernel(const float* __restrict__ src,
                          const float* __restrict__ srcCls,
                          __half* __restrict__ dst,
                          const float* __restrict__ g, const float* __restrict__ b,
                          int mode, int srcOff) {
    int row = blockIdx.x;
    const float* xr;
    if (mode == 0) {
        xr = src + (size_t)(row + srcOff) * CC;
    } else {
        int ls = row / SB, bb = row % SB;
        int t = bb / NB, n = bb % NB;
        if (ls == 0) xr = srcCls + (size_t)n * CC;
        else         xr = src + (size_t)(((ls - 1) * TT + t) * NB + n) * CC;
    }
    int tid = threadIdx.x;
    float s = 0.f, s2 = 0.f;
    float v[4];
    #pragma unroll
    for (int it = 0; it < 4; it++) {
        float val = xr[tid + it * 256];
        v[it] = val; s += val; s2 += val * val;
    }
    __shared__ float red[2][8];
    for (int m = 16; m; m >>= 1) {
        s  += __shfl_xor_sync(~0u, s, m);
        s2 += __shfl_xor_sync(~0u, s2, m);
    }
    if ((tid & 31) == 0) { red[0][tid >> 5] = s; red[1][tid >> 5] = s2; }
    __syncthreads();
    s = 0.f; s2 = 0.f;
    #pragma unroll
    for (int w = 0; w < 8; w++) { s += red[0][w]; s2 += red[1][w]; }
    float mean = s * (1.f / CC);
    float var  = s2 * (1.f / CC) - mean * mean;
    float inv  = rsqrtf(var + 1e-5f);
    __half* dr = dst + (size_t)row * CC;
    #pragma unroll
    for (int it = 0; it < 4; it++) {
        int c = tid + it * 256;
        dr[c] = __float2half_rn((v[it] - mean) * inv * g[c] + b[c]);
    }
}

// ---------------- fused spatial residual + LayerNorm2 ----------------------
__global__ void resid_ln_kernel(const float* __restrict__ g,
                                const float* __restrict__ b) {
    int row = blockIdx.x, tid = threadIdx.x;
    int token = row >> 3, n = row & 7;
    float v[4];
    float s = 0.f, s2 = 0.f;
    #pragma unroll
    for (int it = 0; it < 4; it++) {
        int c = tid + it * 256;
        float base = g_XBUF[(size_t)row * CC + c];
        float add;
        if (token == 0) {
            float a = 0.f;
            #pragma unroll
            for (int t = 0; t < TT; t++)
                a += g_PROJ[((size_t)(t * NB + n)) * CC + c];
            add = a * 0.125f;
        } else {
            int p = token - 1;
            int l = p >> 3, t = p & 7;
            add = g_PROJ[((size_t)((l + 1) * SB + t * NB + n)) * CC + c];
        }
        float vv = base + add;
        g_XBUF[(size_t)row * CC + c] = vv;
        v[it] = vv; s += vv; s2 += vv * vv;
    }
    __shared__ float red[2][8];
    for (int m = 16; m; m >>= 1) {
        s  += __shfl_xor_sync(~0u, s, m);
        s2 += __shfl_xor_sync(~0u, s2, m);
    }
    if ((tid & 31) == 0) { red[0][tid >> 5] = s; red[1][tid >> 5] = s2; }
    __syncthreads();
    s = 0.f; s2 = 0.f;
    #pragma unroll
    for (int w = 0; w < 8; w++) { s += red[0][w]; s2 += red[1][w]; }
    float mean = s * (1.f / CC);
    float var  = s2 * (1.f / CC) - mean * mean;
    float inv  = rsqrtf(var + 1e-5f);
    __half* dr = g_LNh + (size_t)row * CC;
    #pragma unroll
    for (int it = 0; it < 4; it++) {
        int c = tid + it * 256;
        dr[c] = __float2half_rn((v[it] - mean) * inv * g[c] + b[c]);
    }
}

// ---------------- fp16 tensor-core GEMM, cp.async + ldmatrix, BK=32 --------
// (R13-proven config: 4 stages, power-of-2 masks.)
// MODE 0: fp32 store | 1: QuickGELU->fp16 (packed f16x2 MUFU) | 2: residual
// add fp32 | 3: fp16 store
// BATCH 0: none | 1: qkv-layout A/B (scores), S-out | 2: P/Vt in, qkv-scatter out
#define HSTR 40
#define STAGE_HALF (2 * 128 * HSTR)
#define GSTAGES 4
#define GSMEM_BYTES (GSTAGES * STAGE_HALF * 2)  // 81920

template<int MODE, int BATCH>
__global__ void __launch_bounds__(256, 2)
tgemm_kernel(const __half* __restrict__ A, size_t strideA,
             const __half* __restrict__ B, size_t strideB,
             const float* __restrict__ bias, const float* __restrict__ res,
             void* __restrict__ outv, size_t outStride,
             int M, int N, int K, int colLim) {
    extern __shared__ __half smh[];
    const int tid  = threadIdx.x;
    const int bm   = blockIdx.y * 128, bn = blockIdx.x * 128;
    const int z    = blockIdx.z;
    const int lane = tid & 31, wid = tid >> 5;
    const int wm   = (wid & 1) << 6;
    const int wn   = (wid >> 1) << 5;

    size_t aoff = 0, boff = 0, ooff = 0;
    if (BATCH == 1) {
        size_t e = (size_t)(z >> 4) * 3072 + (size_t)(z & 15) * 64;
        aoff = e; boff = e;
        ooff = (size_t)z * LS * SKP;
    } else if (BATCH == 2) {
        aoff = (size_t)z * LS * PKP;
        boff = (size_t)z * HD * PKP;
        ooff = (size_t)(z >> 4) * 1024 + (size_t)(z & 15) * 64;
    }

    const int  lrow  = tid & 127;
    const bool loadA = tid < 128;
    int  growi = loadA ? (bm + lrow) : (bn + lrow);
    const bool valid = loadA ? (growi < M) : (growi < N);
    const int  vsz   = valid ? 16 : 0;
    if (!valid) growi = 0;
    const __half* gRow = (loadA ? (A + aoff) : (B + boff))
                       + (size_t)growi * (loadA ? strideA : strideB);
    unsigned sbase = (unsigned)__cvta_generic_to_shared(smh);
    const unsigned dRowOff = (loadA ? 0u : 128u * HSTR * 2) + lrow * (HSTR * 2);

    unsigned aoff_lm[4], boff_lm[2];
    #pragma unroll
    for (int mt = 0; mt < 4; mt++)
        aoff_lm[mt] = (unsigned)(((wm + mt * 16 + (lane & 15)) * HSTR
                                  + ((lane >> 4) << 3)) * 2);
    #pragma unroll
    for (int p = 0; p < 2; p++)
        boff_lm[p] = (unsigned)(((128 + wn + (2 * p + (lane >> 4)) * 8 + (lane & 7)) * HSTR
                                 + (((lane >> 3) & 1) << 3)) * 2);

    float acc[16][4];
    #pragma unroll
    for (int i = 0; i < 16; i++)
        #pragma unroll
        for (int j = 0; j < 4; j++) acc[i][j] = 0.f;

    const int NS = K >> 5;

    #pragma unroll
    for (int s = 0; s < GSTAGES - 1; s++) {
        if (s < NS) {
            unsigned d = sbase + (unsigned)(s * STAGE_HALF * 2) + dRowOff;
            const __half* gp = gRow + s * 32;
            #pragma unroll
            for (int c = 0; c < 4; c++)
                asm volatile("cp.async.cg.shared.global [%0], [%1], 16, %2;\n"
                             :: "r"(d + c * 16), "l"(gp + c * 8), "r"(vsz));
        }
        asm volatile("cp.async.commit_group;\n");
    }

    for (int s = 0; s < NS; s++) {
        asm volatile("cp.async.wait_group %0;\n" :: "n"(GSTAGES - 2));
        __syncthreads();

        if (s + GSTAGES - 1 < NS) {
            int st = (s + GSTAGES - 1) & (GSTAGES - 1);
            unsigned d = sbase + (unsigned)(st * STAGE_HALF * 2) + dRowOff;
            const __half* gp = gRow + (s + GSTAGES - 1) * 32;
            #pragma unroll
            for (int c = 0; c < 4; c++)
                asm volatile("cp.async.cg.shared.global [%0], [%1], 16, %2;\n"
                             :: "r"(d + c * 16), "l"(gp + c * 8), "r"(vsz));
        }
        asm volatile("cp.async.commit_group;\n");

        const unsigned stb = sbase + (unsigned)((s & (GSTAGES - 1)) * STAGE_HALF * 2);

        #pragma unroll
        for (int kk = 0; kk < 32; kk += 16) {
            unsigned af[4][4], bf[4][2];
            #pragma unroll
            for (int mt = 0; mt < 4; mt++) {
                asm volatile(
                    "ldmatrix.sync.aligned.m8n8.x4.shared.b16 {%0,%1,%2,%3}, [%4];"
                    : "=r"(af[mt][0]), "=r"(af[mt][1]), "=r"(af[mt][2]), "=r"(af[mt][3])
                    : "r"(stb + aoff_lm[mt] + kk * 2));
            }
            #pragma unroll
            for (int p = 0; p < 2; p++) {
                asm volatile(
                    "ldmatrix.sync.aligned.m8n8.x4.shared.b16 {%0,%1,%2,%3}, [%4];"
                    : "=r"(bf[2*p][0]), "=r"(bf[2*p][1]),
                      "=r"(bf[2*p+1][0]), "=r"(bf[2*p+1][1])
                    : "r"(stb + boff_lm[p] + kk * 2));
            }
            #pragma unroll
            for (int mt = 0; mt < 4; mt++)
                #pragma unroll
                for (int nt = 0; nt < 4; nt++) {
                    float* c = acc[mt * 4 + nt];
                    asm volatile(
                        "mma.sync.aligned.m16n8k16.row.col.f32.f16.f16.f32 "
                        "{%0,%1,%2,%3}, {%4,%5,%6,%7}, {%8,%9}, {%0,%1,%2,%3};\n"
                        : "+f"(c[0]), "+f"(c[1]), "+f"(c[2]), "+f"(c[3])
                        : "r"(af[mt][0]), "r"(af[mt][1]), "r"(af[mt][2]), "r"(af[mt][3]),
                          "r"(bf[nt][0]), "r"(bf[nt][1]));
                }
        }
    }

    float*   outF = (float*)outv;
    __half2* outH = (__half2*)outv;
    const int erow = lane >> 2;
    const int ecol = (lane & 3) * 2;
    #pragma unroll
    for (int mt = 0; mt < 4; mt++) {
        #pragma unroll
        for (int nt = 0; nt < 4; nt++) {
            const float* c = acc[mt * 4 + nt];
            int col = bn + wn + nt * 8 + ecol;
            if (col >= colLim) continue;
            float bv0 = bias[col], bv1 = bias[col + 1];
            #pragma unroll
            for (int half = 0; half < 2; half++) {
                int row = bm + wm + mt * 16 + erow + half * 8;
                if (row < M) {
                    size_t off = ooff + (size_t)row * outStride + col;
                    float v0 = c[half * 2 + 0] + bv0;
                    float v1 = c[half * 2 + 1] + bv1;
                    if (MODE == 1) {
                        // QuickGELU via packed f16x2 MUFU:
                        // sigmoid(1.702v) = 1/(1 + 2^(-2.4554668 v))
                        __half2 ty = __floats2half2_rn(-2.4554668f * v0,
                                                       -2.4554668f * v1);
                        __half2 e2 = h2ex2(ty);
                        __half2 r  = h2rcp(__hadd2(__float2half2_rn(1.f), e2));
                        v0 = v0 * __low2float(r);
                        v1 = v1 * __high2float(r);
                        outH[off >> 1] = __floats2half2_rn(v0, v1);
                    } else if (MODE == 3) {
                        outH[off >> 1] = __floats2half2_rn(v0, v1);
                    } else {
                        if (MODE == 2) {
                            v0 += res[off];
                            v1 += res[off + 1];
                        }
                        outF[off]     = v0;
                        outF[off + 1] = v1;
                    }
                }
            }
        }
    }
}

// ---------------- spatial softmax: scale + bias + packed-f16x2 exp ---------
__global__ void softmax_kernel(const float* __restrict__ rpb_s) {
    int wid = threadIdx.x >> 5, lane = threadIdx.x & 31;
    int q = blockIdx.x * 4 + wid;
    if (q >= LS) return;
    int b = blockIdx.y, h = blockIdx.z;
    size_t sbase = ((size_t)(b * 16 + h) * LS + q) * SKP;
    size_t pbase = ((size_t)(b * 16 + h) * LS + q) * PKP;
    int qi = 0, qj = 0;
    if (q > 0) { qi = (q - 1) / SS; qj = (q - 1) % SS; }
    float sv[7];
    float mx = -1e30f;
    #pragma unroll
    for (int it = 0; it < 7; it++) {
        int k = lane + it * 32;
        float s = -1e30f;
        if (k < LS) {
            s = g_S[sbase + k] * 0.125f;
            if (q > 0 && k > 0) {
                int ki = (k - 1) / SS, kj = (k - 1) % SS;
                int idx = (qi - ki + SS - 1) * (2 * SS - 1) + (qj - kj + SS - 1);
                s += rpb_s[idx * NH + h];
            }
        }
        sv[it] = s;
        mx = fmaxf(mx, s);
    }
    for (int m = 16; m; m >>= 1) mx = fmaxf(mx, __shfl_xor_sync(~0u, mx, m));
    // exp via packed ex2.approx.f16x2 (invalid slots -> huge negative -> 0)
    float sum = 0.f;
    #pragma unroll
    for (int it = 0; it < 7; it += 2) {
        float y0 = (sv[it] - mx) * 1.44269504f;
        float y1 = (it + 1 < 7) ? (sv[it + 1] - mx) * 1.44269504f : -60.f;
        if (y0 < -60.f) y0 = -60.f;
        if (y1 < -60.f) y1 = -60.f;
        __half2 he = h2ex2(__floats2half2_rn(y0, y1));
        float e0 = __low2float(he), e1 = __high2float(he);
        sv[it] = e0; sum += e0;
        if (it + 1 < 7) { sv[it + 1] = e1; sum += e1; }
    }
    for (int m = 16; m; m >>= 1) sum += __shfl_xor_sync(~0u, sum, m);
    float inv = 1.f / sum;
    #pragma unroll
    for (int it = 0; it < 7; it++) {
        int k = lane + it * 32;
        if (k < LS) g_P[pbase + k] = __float2half_rn(sv[it] * inv);
    }
    for (int k = LS + lane; k < PKP; k += 32)
        g_P[pbase + k] = __ushort_as_half(0);
}

// ---------------- V transpose: Vt[bh][d][key] fp16, key-padded -------------
__global__ void vt_kernel() {
    __shared__ unsigned vsm[LS * 33];
    int z = blockIdx.x;
    int b = z >> 4, h = z & 15;
    int tid = threadIdx.x;
    for (int idx = tid; idx < LS * 32; idx += 256) {
        int ls = idx >> 5, dp = idx & 31;
        vsm[ls * 33 + dp] = *(const unsigned*)
            (g_QKVh + ((size_t)(ls * SB + b)) * 3072 + 2048 + h * 64 + dp * 2);
    }
    __syncthreads();
    const __half* vh = (const __half*)vsm;
    __half2* dst = (__half2*)(g_Vt + (size_t)z * HD * PKP);
    for (int idx = tid; idx < HD * (PKP / 2); idx += 256) {
        int d = idx / (PKP / 2), kp = idx % (PKP / 2);
        __half h0 = (2 * kp     < LS) ? vh[(2 * kp)     * 66 + d] : __ushort_as_half(0);
        __half h1 = (2 * kp + 1 < LS) ? vh[(2 * kp + 1) * 66 + d] : __ushort_as_half(0);
        dst[(size_t)d * (PKP / 2) + kp] = __halves2half2(h0, h1);
    }
}

// ---------------- Temporal attention: block = (l,n), all 16 heads ----------
#define TSTR 3080   // halves per token row: 3072 + 8 pad
#define TATT_SMEM (TT * TSTR * 2)   // 49280 bytes (dynamic)
__global__ void __launch_bounds__(256)
temporal_attn_kernel(const float* __restrict__ rpb_t) {
    extern __shared__ __half sm[];
    __shared__ float Psm[NH][TT][TT];
    int bid = blockIdx.x;           // 0..1567
    int n = bid & 7, l = bid >> 3;
    int tid = threadIdx.x, wid = tid >> 5, lane = tid & 31;

    uint4* dsm = (uint4*)sm;        // TSTR/8 = 385 uint4 per row
    for (int idx = tid; idx < TT * 384; idx += 256) {
        int t = idx / 384, u = idx % 384;
        size_t r = (size_t)((l * TT + t) * NB + n);
        dsm[t * 385 + u] = ((const uint4*)(g_QKVh + r * 3072))[u];
    }
    __syncthreads();

    #pragma unroll
    for (int hh = 0; hh < 2; hh++) {
        int h = wid * 2 + hh;
        float sv[2];
        #pragma unroll
        for (int pp = 0; pp < 2; pp++) {
            int p = lane + pp * 32;
            int tq = p >> 3, tk = p & 7;
            const __half2* qp = (const __half2*)(sm + tq * TSTR + h * HD);
            const __half2* kp = (const __half2*)(sm + tk * TSTR + 1024 + h * HD);
            float acc = 0.f;
            #pragma unroll
            for (int d2 = 0; d2 < 32; d2++) {
                float2 qv = __half22float2(qp[d2]);
                float2 kv = __half22float2(kp[d2]);
                acc += qv.x * kv.x + qv.y * kv.y;
            }
            sv[pp] = acc * 0.125f + rpb_t[(tq - tk + TT - 1) * NH + h];
        }
        #pragma unroll
        for (int pp = 0; pp < 2; pp++) {
            float m = sv[pp];
            for (int msk = 4; msk; msk >>= 1)
                m = fmaxf(m, __shfl_xor_sync(~0u, m, msk));
            float e = expf(sv[pp] - m);
            float su = e;
            for (int msk = 4; msk; msk >>= 1)
                su += __shfl_xor_sync(~0u, su, msk);
            sv[pp] = e / su;
        }
        Psm[h][lane >> 3][lane & 7]       = sv[0];
        Psm[h][4 + (lane >> 3)][lane & 7] = sv[1];
        __syncwarp();
        float2 o[TT];
        #pragma unroll
        for (int t = 0; t < TT; t++) { o[t].x = 0.f; o[t].y = 0.f; }
        #pragma unroll
        for (int k = 0; k < TT; k++) {
            float2 vv = __half22float2(
                *(const __half2*)(sm + k * TSTR + 2048 + h * HD + 2 * lane));
            #pragma unroll
            for (int t = 0; t < TT; t++) {
                float pkt = Psm[h][t][k];
                o[t].x += pkt * vv.x;
                o[t].y += pkt * vv.y;
            }
        }
        #pragma unroll
        for (int t = 0; t < TT; t++) {
            size_t r = (size_t)((l * TT + t) * NB + n);
            *(__half2*)(g_ATTh + r * CC + h * HD + 2 * lane) =
                __floats2half2_rn(o[t].x, o[t].y);
        }
        __syncwarp();
    }
}

// ---------------------------------------------------------------------------
extern "C" void kernel_launch(void* const* d_in, const int* in_sizes, int n_in,
                              void* d_out, int out_size) {
    const float* x      = (const float*)d_in[0];
    const float* pos_w  = (const float*)d_in[1];
    const float* pos_b  = (const float*)d_in[2];
    const float* ln_t_g = (const float*)d_in[3];
    const float* ln_t_b = (const float*)d_in[4];
    const float* rpb_t  = (const float*)d_in[5];
    const float* wqkv_t = (const float*)d_in[6];
    const float* bqkv_t = (const float*)d_in[7];
    const float* wo_t   = (const float*)d_in[8];
    const float* bo_t   = (const float*)d_in[9];
    const float* ln1_g  = (const float*)d_in[10];
    const float* ln1_b  = (const float*)d_in[11];
    const float* rpb_s  = (const float*)d_in[12];
    const float* wqkv_s = (const float*)d_in[13];
    const float* bqkv_s = (const float*)d_in[14];
    const float* wo_s   = (const float*)d_in[15];
    const float* bo_s   = (const float*)d_in[16];
    const float* ln2_g  = (const float*)d_in[17];
    const float* ln2_b  = (const float*)d_in[18];
    const float* fc_w   = (const float*)d_in[19];
    const float* fc_b   = (const float*)d_in[20];
    const float* proj_w = (const float*)d_in[21];
    const float* proj_b = (const float*)d_in[22];
    float* out = (float*)d_out;

    float *pX, *pPROJ, *pXT, *pS, *pZERO;
    __half *pLNh, *pQKVh, *pATTh, *pHh, *pWTh, *pP, *pVt;
    cudaGetSymbolAddress((void**)&pX,    g_XBUF);
    cudaGetSymbolAddress((void**)&pLNh,  g_LNh);
    cudaGetSymbolAddress((void**)&pQKVh, g_QKVh);
    cudaGetSymbolAddress((void**)&pATTh, g_ATTh);
    cudaGetSymbolAddress((void**)&pPROJ, g_PROJ);
    cudaGetSymbolAddress((void**)&pXT,   g_XT);
    cudaGetSymbolAddress((void**)&pHh,   g_Hh);
    cudaGetSymbolAddress((void**)&pWTh,  g_WTh);
    cudaGetSymbolAddress((void**)&pS,    g_S);
    cudaGetSymbolAddress((void**)&pP,    g_P);
    cudaGetSymbolAddress((void**)&pVt,   g_Vt);
    cudaGetSymbolAddress((void**)&pZERO, g_ZERO);

    #define SET_SMEM(k, sz) cudaFuncSetAttribute(k, \
        cudaFuncAttributeMaxDynamicSharedMemorySize, sz)
    SET_SMEM((tgemm_kernel<0,0>), GSMEM_BYTES);
    SET_SMEM((tgemm_kernel<1,0>), GSMEM_BYTES);
    SET_SMEM((tgemm_kernel<2,0>), GSMEM_BYTES);
    SET_SMEM((tgemm_kernel<3,0>), GSMEM_BYTES);
    SET_SMEM((tgemm_kernel<0,1>), GSMEM_BYTES);
    SET_SMEM((tgemm_kernel<3,2>), GSMEM_BYTES);
    SET_SMEM(temporal_attn_kernel, TATT_SMEM);

    // fp16 weight copies (contiguous arena; one merged prep launch)
    __half* wqkvT = pWTh;
    __half* woT   = pWTh + 3145728;
    __half* wqkvS = pWTh + 4194304;
    __half* woS   = pWTh + 7340032;
    __half* fcW   = pWTh + 8388608;
    __half* projW = pWTh + 12582912;
    W6 ws;
    ws.p[0] = wqkv_t; ws.p[1] = wo_t; ws.p[2] = wqkv_s;
    ws.p[3] = wo_s;   ws.p[4] = fc_w; ws.p[5] = proj_w;
    wprep_all_kernel<<<16384, 256>>>(ws, pWTh);

    // Stage 1+LN_t fused: conv pos embed -> XBUF, LN_t -> LNh
    pos_ln_kernel<<<dim3(LL, NB), 256>>>(x, pos_w, pos_b, ln_t_g, ln_t_b);

    // Stage 2: temporal attention on patch rows -> xt_full (fp32) in pXT
    tgemm_kernel<3,0><<<dim3(24, 98, 1), 256, GSMEM_BYTES>>>(
        pLNh, 1024, wqkvT, 1024, bqkv_t, nullptr, pQKVh, 3072,
        PROWS, 3072, 1024, 3072);
    temporal_attn_kernel<<<LL * NB, 256, TATT_SMEM>>>(rpb_t);
    tgemm_kernel<2,0><<<dim3(8, 98, 1), 256, GSMEM_BYTES>>>(
        pATTh, 1024, woT, 1024, bo_t, pX + (size_t)NB * CC, pXT, 1024,
        PROWS, 1024, 1024, 1024);

    // Stage 3: spatial attention (seq 197 incl. cls) via batched GEMMs
    ln_kernel<<<SROWS, 256>>>(pXT, pX, pLNh, ln1_g, ln1_b, 1, 0);
    tgemm_kernel<3,0><<<dim3(24, 99, 1), 256, GSMEM_BYTES>>>(
        pLNh, 1024, wqkvS, 1024, bqkv_s, nullptr, pQKVh, 3072,
        SROWS, 3072, 1024, 3072);
    tgemm_kernel<0,1><<<dim3(2, 2, BH), 256, GSMEM_BYTES>>>(
        pQKVh, (size_t)SB * 3072, pQKVh + 1024, (size_t)SB * 3072,
        pZERO, nullptr, pS, SKP, LS, LS, 64, 198);
    softmax_kernel<<<dim3((LS + 3) / 4, SB, NH), 128>>>(rpb_s);
    vt_kernel<<<BH, 256>>>();
    tgemm_kernel<3,2><<<dim3(1, 2, BH), 256, GSMEM_BYTES>>>(
        pP, PKP, pVt, PKP, pZERO, nullptr, pATTh, (size_t)SB * 1024,
        LS, HD, PKP, HD);
    tgemm_kernel<0,0><<<dim3(8, 99, 1), 256, GSMEM_BYTES>>>(
        pATTh, 1024, woS, 1024, bo_s, nullptr, pPROJ, 1024,
        SROWS, 1024, 1024, 1024);

    // fused: spatial residual (+cls mean) into XBUF, then LN2 -> LNh
    resid_ln_kernel<<<ROWS, 256>>>(ln2_g, ln2_b);

    // Stage 4: MLP with QuickGELU (hidden in fp16)
    tgemm_kernel<1,0><<<dim3(32, 99, 1), 256, GSMEM_BYTES>>>(
        pLNh, 1024, fcW, 1024, fc_b, nullptr, pHh, 4096,
        ROWS, 4096, 1024, 4096);
    tgemm_kernel<2,0><<<dim3(8, 99, 1), 256, GSMEM_BYTES>>>(
        pHh, 4096, projW, 4096, proj_b, pX, out, 1024,
        ROWS, 1024, 4096, 1024);
}